// round 1
// baseline (speedup 1.0000x reference)
#include <cuda_runtime.h>
#include <math.h>

#define T_TOK 4096
#define HDIM  2048
#define NEXP  16
#define TOPK  4
#define FE    1408
#define FS    5632

// Scratch: max(T*K*FE, T*FS) floats -- both are exactly 23,068,672 (92.3 MB)
__device__ float g_hdn[23068672];
__device__ int   g_selE[T_TOK * TOPK];
__device__ float g_selW[T_TOK * TOPK];
__device__ int   g_rowtok[T_TOK * TOPK];
__device__ float g_roww[T_TOK * TOPK];
__device__ float g_sgate[T_TOK];
__device__ int   g_cnt[NEXP];
__device__ int   g_off[NEXP + 1];
__device__ int   g_cur[NEXP];

// ---------------------------------------------------------------------------
// init: zero expert counters (graph replays must be deterministic)
// ---------------------------------------------------------------------------
__global__ void k_init() {
    if (threadIdx.x < NEXP) g_cnt[threadIdx.x] = 0;
}

// ---------------------------------------------------------------------------
// Router: one warp per token.
// logits = x @ gate_w^T ; softmax fp32 ; top-4 ; renorm ; also sigmoid shared gate
// ---------------------------------------------------------------------------
__global__ void k_router(const float* __restrict__ X,
                         const float* __restrict__ GW,
                         const float* __restrict__ SEGW) {
    int warp = (blockIdx.x * blockDim.x + threadIdx.x) >> 5;
    int lane = threadIdx.x & 31;
    if (warp >= T_TOK) return;
    const float* xr = X + (size_t)warp * HDIM;

    float part[NEXP];
    float ps = 0.f;
#pragma unroll
    for (int e = 0; e < NEXP; e++) part[e] = 0.f;

    for (int h = lane; h < HDIM; h += 32) {
        float xv = xr[h];
#pragma unroll
        for (int e = 0; e < NEXP; e++) part[e] += xv * GW[e * HDIM + h];
        ps += xv * SEGW[h];
    }
#pragma unroll
    for (int e = 0; e < NEXP; e++) {
#pragma unroll
        for (int o = 16; o > 0; o >>= 1)
            part[e] += __shfl_down_sync(0xffffffffu, part[e], o);
    }
#pragma unroll
    for (int o = 16; o > 0; o >>= 1)
        ps += __shfl_down_sync(0xffffffffu, ps, o);

    if (lane == 0) {
        float m = part[0];
#pragma unroll
        for (int e = 1; e < NEXP; e++) m = fmaxf(m, part[e]);
        float r[NEXP];
        float den = 0.f;
#pragma unroll
        for (int e = 0; e < NEXP; e++) { r[e] = expf(part[e] - m); den += r[e]; }
        float inv = 1.f / den;
#pragma unroll
        for (int e = 0; e < NEXP; e++) r[e] *= inv;

        int   se[TOPK];
        float sw[TOPK];
        float s4 = 0.f;
#pragma unroll
        for (int k = 0; k < TOPK; k++) {
            int bi = 0; float bv = -1.f;
#pragma unroll
            for (int e = 0; e < NEXP; e++)
                if (r[e] > bv) { bv = r[e]; bi = e; }
            se[k] = bi; sw[k] = bv; s4 += bv;
            r[bi] = -2.f;
        }
        float invs4 = 1.f / s4;
#pragma unroll
        for (int k = 0; k < TOPK; k++) {
            g_selE[warp * TOPK + k] = se[k];
            g_selW[warp * TOPK + k] = sw[k] * invs4;
            atomicAdd(&g_cnt[se[k]], 1);
        }
        g_sgate[warp] = 1.f / (1.f + expf(-ps));
    }
}

// ---------------------------------------------------------------------------
// offsets: exclusive prefix over 16 counts; zero assignment cursors
// ---------------------------------------------------------------------------
__global__ void k_offsets() {
    if (threadIdx.x == 0) {
        int acc = 0;
        for (int e = 0; e < NEXP; e++) {
            g_off[e] = acc;
            acc += g_cnt[e];
            g_cur[e] = 0;
        }
        g_off[NEXP] = acc;
    }
}

// ---------------------------------------------------------------------------
// assign: build compact per-expert (token, weight) lists
// ---------------------------------------------------------------------------
__global__ void k_assign() {
    int t = blockIdx.x * blockDim.x + threadIdx.x;
    if (t >= T_TOK) return;
#pragma unroll
    for (int k = 0; k < TOPK; k++) {
        int e = g_selE[t * TOPK + k];
        int slot = atomicAdd(&g_cur[e], 1);
        int pos = g_off[e] + slot;
        g_rowtok[pos] = t;
        g_roww[pos] = g_selW[t * TOPK + k];
    }
}

// ---------------------------------------------------------------------------
// Fused gate+up GEMM with silu(g)*u epilogue.
// C[i,j] = sum_k A[i,k] * W[j,k]   (both row-major, contract over last dim)
// Tile: 128x64, BK=16, 256 threads, 8x4 per-thread per output matrix.
// GATHER=1: per-expert gathered token rows; GATHER=0: shared expert (identity)
// ---------------------------------------------------------------------------
template <int GATHER>
__global__ void __launch_bounds__(256, 2)
k_gateup(const float* __restrict__ X,
         const float* __restrict__ Wgb,
         const float* __restrict__ Wub,
         int N, int Kd) {
    int rows, base;
    const float* Wg;
    const float* Wu;
    if (GATHER) {
        int e = blockIdx.z;
        rows = g_cnt[e];
        base = g_off[e];
        size_t wo = (size_t)e * N * Kd;
        Wg = Wgb + wo; Wu = Wub + wo;
    } else {
        rows = T_TOK; base = 0; Wg = Wgb; Wu = Wub;
    }
    int rowBase = blockIdx.y * 128;
    if (rowBase >= rows) return;
    int colBase = blockIdx.x * 64;

    __shared__ float As[16][132];
    __shared__ float Bgs[16][68];
    __shared__ float Bus[16][68];

    int tid = threadIdx.x;
    int tx = tid & 15;   // col group: 4 cols
    int ty = tid >> 4;   // row group: 8 rows

    float accg[8][4];
    float accu[8][4];
#pragma unroll
    for (int i = 0; i < 8; i++)
#pragma unroll
        for (int j = 0; j < 4; j++) { accg[i][j] = 0.f; accu[i][j] = 0.f; }

    for (int k0 = 0; k0 < Kd; k0 += 16) {
        // A tile: 128 rows x 16 cols (gathered)
#pragma unroll
        for (int i = 0; i < 2; i++) {
            int idx = tid + i * 256;
            int r = idx >> 2;
            int c4 = idx & 3;
            float4 v = make_float4(0.f, 0.f, 0.f, 0.f);
            int grow = rowBase + r;
            if (grow < rows) {
                int tok = GATHER ? g_rowtok[base + grow] : grow;
                v = *reinterpret_cast<const float4*>(X + (size_t)tok * Kd + k0 + c4 * 4);
            }
            As[c4 * 4 + 0][r] = v.x;
            As[c4 * 4 + 1][r] = v.y;
            As[c4 * 4 + 2][r] = v.z;
            As[c4 * 4 + 3][r] = v.w;
        }
        // B tiles: 64 rows x 16 cols each
        {
            int r = tid >> 2;
            int c4 = tid & 3;
            const float4 vg = *reinterpret_cast<const float4*>(
                Wg + (size_t)(colBase + r) * Kd + k0 + c4 * 4);
            Bgs[c4 * 4 + 0][r] = vg.x;
            Bgs[c4 * 4 + 1][r] = vg.y;
            Bgs[c4 * 4 + 2][r] = vg.z;
            Bgs[c4 * 4 + 3][r] = vg.w;
            const float4 vu = *reinterpret_cast<const float4*>(
                Wu + (size_t)(colBase + r) * Kd + k0 + c4 * 4);
            Bus[c4 * 4 + 0][r] = vu.x;
            Bus[c4 * 4 + 1][r] = vu.y;
            Bus[c4 * 4 + 2][r] = vu.z;
            Bus[c4 * 4 + 3][r] = vu.w;
        }
        __syncthreads();
#pragma unroll
        for (int kk = 0; kk < 16; kk++) {
            float4 a0 = *reinterpret_cast<const float4*>(&As[kk][ty * 8]);
            float4 a1 = *reinterpret_cast<const float4*>(&As[kk][ty * 8 + 4]);
            float4 bg = *reinterpret_cast<const float4*>(&Bgs[kk][tx * 4]);
            float4 bu = *reinterpret_cast<const float4*>(&Bus[kk][tx * 4]);
            float a[8] = {a0.x, a0.y, a0.z, a0.w, a1.x, a1.y, a1.z, a1.w};
            float bgv[4] = {bg.x, bg.y, bg.z, bg.w};
            float buv[4] = {bu.x, bu.y, bu.z, bu.w};
#pragma unroll
            for (int i = 0; i < 8; i++) {
#pragma unroll
                for (int j = 0; j < 4; j++) {
                    accg[i][j] += a[i] * bgv[j];
                    accu[i][j] += a[i] * buv[j];
                }
            }
        }
        __syncthreads();
    }

    // epilogue: silu(g) * u -> g_hdn
#pragma unroll
    for (int i = 0; i < 8; i++) {
        int grow = rowBase + ty * 8 + i;
        if (grow >= rows) continue;
        float4 hv;
        float g0 = accg[i][0], g1 = accg[i][1], g2 = accg[i][2], g3 = accg[i][3];
        hv.x = (g0 / (1.f + expf(-g0))) * accu[i][0];
        hv.y = (g1 / (1.f + expf(-g1))) * accu[i][1];
        hv.z = (g2 / (1.f + expf(-g2))) * accu[i][2];
        hv.w = (g3 / (1.f + expf(-g3))) * accu[i][3];
        *reinterpret_cast<float4*>(
            &g_hdn[(size_t)(base + grow) * N + colBase + tx * 4]) = hv;
    }
}

// ---------------------------------------------------------------------------
// Down-projection GEMM with weighted atomic scatter into the output.
// A = g_hdn (compact rows, stride Kd), B = down weight [N, Kd] row-major.
// Out[token, col] += w(row) * sum_k A[row,k] * B[col,k]
// ---------------------------------------------------------------------------
template <int GATHER>
__global__ void __launch_bounds__(256, 2)
k_down(const float* __restrict__ Wdb,
       float* __restrict__ Out,
       int N, int Kd) {
    int rows, base;
    const float* Wd;
    if (GATHER) {
        int e = blockIdx.z;
        rows = g_cnt[e];
        base = g_off[e];
        Wd = Wdb + (size_t)e * N * Kd;
    } else {
        rows = T_TOK; base = 0; Wd = Wdb;
    }
    int rowBase = blockIdx.y * 128;
    if (rowBase >= rows) return;
    int colBase = blockIdx.x * 64;

    __shared__ float As[16][132];
    __shared__ float Bs[16][68];

    int tid = threadIdx.x;
    int tx = tid & 15;
    int ty = tid >> 4;

    float acc[8][4];
#pragma unroll
    for (int i = 0; i < 8; i++)
#pragma unroll
        for (int j = 0; j < 4; j++) acc[i][j] = 0.f;

    for (int k0 = 0; k0 < Kd; k0 += 16) {
#pragma unroll
        for (int i = 0; i < 2; i++) {
            int idx = tid + i * 256;
            int r = idx >> 2;
            int c4 = idx & 3;
            float4 v = make_float4(0.f, 0.f, 0.f, 0.f);
            int grow = rowBase + r;
            if (grow < rows) {
                v = *reinterpret_cast<const float4*>(
                    &g_hdn[(size_t)(base + grow) * Kd + k0 + c4 * 4]);
            }
            As[c4 * 4 + 0][r] = v.x;
            As[c4 * 4 + 1][r] = v.y;
            As[c4 * 4 + 2][r] = v.z;
            As[c4 * 4 + 3][r] = v.w;
        }
        {
            int r = tid >> 2;
            int c4 = tid & 3;
            const float4 vb = *reinterpret_cast<const float4*>(
                Wd + (size_t)(colBase + r) * Kd + k0 + c4 * 4);
            Bs[c4 * 4 + 0][r] = vb.x;
            Bs[c4 * 4 + 1][r] = vb.y;
            Bs[c4 * 4 + 2][r] = vb.z;
            Bs[c4 * 4 + 3][r] = vb.w;
        }
        __syncthreads();
#pragma unroll
        for (int kk = 0; kk < 16; kk++) {
            float4 a0 = *reinterpret_cast<const float4*>(&As[kk][ty * 8]);
            float4 a1 = *reinterpret_cast<const float4*>(&As[kk][ty * 8 + 4]);
            float4 bv = *reinterpret_cast<const float4*>(&Bs[kk][tx * 4]);
            float a[8] = {a0.x, a0.y, a0.z, a0.w, a1.x, a1.y, a1.z, a1.w};
            float b[4] = {bv.x, bv.y, bv.z, bv.w};
#pragma unroll
            for (int i = 0; i < 8; i++)
#pragma unroll
                for (int j = 0; j < 4; j++)
                    acc[i][j] += a[i] * b[j];
        }
        __syncthreads();
    }

#pragma unroll
    for (int i = 0; i < 8; i++) {
        int grow = rowBase + ty * 8 + i;
        if (grow >= rows) continue;
        int tok;
        float w;
        if (GATHER) {
            tok = g_rowtok[base + grow];
            w = g_roww[base + grow];
        } else {
            tok = grow;
            w = g_sgate[grow];
        }
        float* op = Out + (size_t)tok * N + colBase + tx * 4;
        atomicAdd(op + 0, w * acc[i][0]);
        atomicAdd(op + 1, w * acc[i][1]);
        atomicAdd(op + 2, w * acc[i][2]);
        atomicAdd(op + 3, w * acc[i][3]);
    }
}

// ---------------------------------------------------------------------------
extern "C" void kernel_launch(void* const* d_in, const int* in_sizes, int n_in,
                              void* d_out, int out_size) {
    const float* x    = (const float*)d_in[0];  // [B,S,H]
    const float* gw   = (const float*)d_in[1];  // [E,H]
    const float* egw  = (const float*)d_in[2];  // [E,FE,H]
    const float* euw  = (const float*)d_in[3];  // [E,FE,H]
    const float* edw  = (const float*)d_in[4];  // [E,H,FE]
    const float* sgw  = (const float*)d_in[5];  // [FS,H]
    const float* suw  = (const float*)d_in[6];  // [FS,H]
    const float* sdw  = (const float*)d_in[7];  // [H,FS]
    const float* segw = (const float*)d_in[8];  // [1,H]
    float* out = (float*)d_out;

    cudaMemsetAsync(out, 0, sizeof(float) * (size_t)out_size, 0);
    k_init<<<1, 32>>>();
    k_router<<<T_TOK / 8, 256>>>(x, gw, segw);
    k_offsets<<<1, 32>>>();
    k_assign<<<T_TOK / 256, 256>>>();

    // Expert gate+up (gathered): N=FE, K=H
    k_gateup<1><<<dim3(FE / 64, T_TOK / 128, NEXP), 256>>>(x, egw, euw, FE, HDIM);
    // Expert down + weighted scatter: N=H, K=FE
    k_down<1><<<dim3(HDIM / 64, T_TOK / 128, NEXP), 256>>>(edw, out, HDIM, FE);

    // Shared expert gate+up: N=FS, K=H (reuses g_hdn scratch)
    k_gateup<0><<<dim3(FS / 64, T_TOK / 128, 1), 256>>>(x, sgw, suw, FS, HDIM);
    // Shared down, weighted by sigmoid gate: N=H, K=FS
    k_down<0><<<dim3(HDIM / 64, T_TOK / 128, 1), 256>>>(sdw, out, HDIM, FS);
}

// round 11
// speedup vs baseline: 1.0317x; 1.0317x over previous
#include <cuda_runtime.h>
#include <cstdint>
#include <math.h>

#define T_TOK 4096
#define HDIM  2048
#define NEXP  16
#define TOPK  4
#define FE    1408
#define FS    5632

// Scratch: max(T*K*FE, T*FS) floats -- both exactly 23,068,672 (92.3 MB)
__device__ float g_hdn[23068672];
__device__ int   g_selE[T_TOK * TOPK];
__device__ float g_selW[T_TOK * TOPK];
__device__ int   g_rowtok[T_TOK * TOPK];
__device__ float g_roww[T_TOK * TOPK];
__device__ float g_sgate[T_TOK];
__device__ int   g_cnt[NEXP];
__device__ int   g_off[NEXP + 1];
__device__ int   g_cur[NEXP];

// ---------------------------------------------------------------------------
__global__ void k_init() {
    if (threadIdx.x < NEXP) g_cnt[threadIdx.x] = 0;
}

// ---------------------------------------------------------------------------
// Router: one warp per token (proven)
// ---------------------------------------------------------------------------
__global__ void k_router(const float* __restrict__ X,
                         const float* __restrict__ GW,
                         const float* __restrict__ SEGW) {
    int warp = (blockIdx.x * blockDim.x + threadIdx.x) >> 5;
    int lane = threadIdx.x & 31;
    if (warp >= T_TOK) return;
    const float* xr = X + (size_t)warp * HDIM;

    float part[NEXP];
    float ps = 0.f;
#pragma unroll
    for (int e = 0; e < NEXP; e++) part[e] = 0.f;

    for (int h = lane; h < HDIM; h += 32) {
        float xv = xr[h];
#pragma unroll
        for (int e = 0; e < NEXP; e++) part[e] += xv * GW[e * HDIM + h];
        ps += xv * SEGW[h];
    }
#pragma unroll
    for (int e = 0; e < NEXP; e++) {
#pragma unroll
        for (int o = 16; o > 0; o >>= 1)
            part[e] += __shfl_down_sync(0xffffffffu, part[e], o);
    }
#pragma unroll
    for (int o = 16; o > 0; o >>= 1)
        ps += __shfl_down_sync(0xffffffffu, ps, o);

    if (lane == 0) {
        float m = part[0];
#pragma unroll
        for (int e = 1; e < NEXP; e++) m = fmaxf(m, part[e]);
        float r[NEXP];
        float den = 0.f;
#pragma unroll
        for (int e = 0; e < NEXP; e++) { r[e] = expf(part[e] - m); den += r[e]; }
        float inv = 1.f / den;
#pragma unroll
        for (int e = 0; e < NEXP; e++) r[e] *= inv;

        int   se[TOPK];
        float sw[TOPK];
        float s4 = 0.f;
#pragma unroll
        for (int k = 0; k < TOPK; k++) {
            int bi = 0; float bv = -1.f;
#pragma unroll
            for (int e = 0; e < NEXP; e++)
                if (r[e] > bv) { bv = r[e]; bi = e; }
            se[k] = bi; sw[k] = bv; s4 += bv;
            r[bi] = -2.f;
        }
        float invs4 = 1.f / s4;
#pragma unroll
        for (int k = 0; k < TOPK; k++) {
            g_selE[warp * TOPK + k] = se[k];
            g_selW[warp * TOPK + k] = sw[k] * invs4;
            atomicAdd(&g_cnt[se[k]], 1);
        }
        g_sgate[warp] = 1.f / (1.f + expf(-ps));
    }
}

// ---------------------------------------------------------------------------
__global__ void k_offsets() {
    if (threadIdx.x == 0) {
        int acc = 0;
        for (int e = 0; e < NEXP; e++) {
            g_off[e] = acc;
            acc += g_cnt[e];
            g_cur[e] = 0;
        }
        g_off[NEXP] = acc;
    }
}

// ---------------------------------------------------------------------------
__global__ void k_assign() {
    int t = blockIdx.x * blockDim.x + threadIdx.x;
    if (t >= T_TOK) return;
#pragma unroll
    for (int k = 0; k < TOPK; k++) {
        int e = g_selE[t * TOPK + k];
        int slot = atomicAdd(&g_cur[e], 1);
        int pos = g_off[e] + slot;
        g_rowtok[pos] = t;
        g_roww[pos] = g_selW[t * TOPK + k];
    }
}

// ---------------------------------------------------------------------------
// Packed fp32x2 helpers (Blackwell fma.rn.f32x2: 2 exact fp32 FMAs / instr)
// ---------------------------------------------------------------------------
__device__ __forceinline__ unsigned long long pk2(float x) {
    unsigned long long r;
    asm("mov.b64 %0, {%1, %1};" : "=l"(r) : "f"(x));
    return r;
}
__device__ __forceinline__ void fma2(unsigned long long& d,
                                     unsigned long long a,
                                     unsigned long long b) {
    asm("fma.rn.f32x2 %0, %1, %2, %0;" : "+l"(d) : "l"(a), "l"(b));
}
__device__ __forceinline__ float2 up2(unsigned long long v) {
    float lo, hi;
    asm("mov.b64 {%0, %1}, %2;" : "=f"(lo), "=f"(hi) : "l"(v));
    return make_float2(lo, hi);
}

// ---------------------------------------------------------------------------
// Fused gate+up GEMM (FFMA2). Tile 128x64, BK=16, 256 threads.
// Per-thread: 8 rows (as 4 row-pairs) x 4 cols, two accumulator sets.
// GATHER=1: per-expert gathered rows; GATHER=0: shared expert.
// ---------------------------------------------------------------------------
template <int GATHER>
__global__ void __launch_bounds__(256, 2)
k_gateup(const float* __restrict__ X,
         const float* __restrict__ Wgb,
         const float* __restrict__ Wub,
         int N, int Kd) {
    int rows, base;
    const float* Wg;
    const float* Wu;
    if (GATHER) {
        int e = blockIdx.z;
        rows = g_cnt[e];
        base = g_off[e];
        size_t wo = (size_t)e * N * Kd;
        Wg = Wgb + wo; Wu = Wub + wo;
    } else {
        rows = T_TOK; base = 0; Wg = Wgb; Wu = Wub;
    }
    int rowBase = blockIdx.y * 128;
    if (rowBase >= rows) return;
    int colBase = blockIdx.x * 64;

    __shared__ float As[16][132];
    __shared__ float Bgs[16][68];
    __shared__ float Bus[16][68];

    int tid = threadIdx.x;
    int tx = tid & 15;   // col group: 4 cols
    int ty = tid >> 4;   // row group: 8 rows

    unsigned long long accg2[4][4];
    unsigned long long accu2[4][4];
#pragma unroll
    for (int p = 0; p < 4; p++)
#pragma unroll
        for (int j = 0; j < 4; j++) { accg2[p][j] = 0ULL; accu2[p][j] = 0ULL; }

    for (int k0 = 0; k0 < Kd; k0 += 16) {
        // A tile: 128 rows x 16 cols (gathered)
#pragma unroll
        for (int i = 0; i < 2; i++) {
            int idx = tid + i * 256;
            int r = idx >> 2;
            int c4 = idx & 3;
            float4 v = make_float4(0.f, 0.f, 0.f, 0.f);
            int grow = rowBase + r;
            if (grow < rows) {
                int tok = GATHER ? g_rowtok[base + grow] : grow;
                v = *reinterpret_cast<const float4*>(X + (size_t)tok * Kd + k0 + c4 * 4);
            }
            As[c4 * 4 + 0][r] = v.x;
            As[c4 * 4 + 1][r] = v.y;
            As[c4 * 4 + 2][r] = v.z;
            As[c4 * 4 + 3][r] = v.w;
        }
        // B tiles: 64 rows x 16 cols each
        {
            int r = tid >> 2;
            int c4 = tid & 3;
            const float4 vg = *reinterpret_cast<const float4*>(
                Wg + (size_t)(colBase + r) * Kd + k0 + c4 * 4);
            Bgs[c4 * 4 + 0][r] = vg.x;
            Bgs[c4 * 4 + 1][r] = vg.y;
            Bgs[c4 * 4 + 2][r] = vg.z;
            Bgs[c4 * 4 + 3][r] = vg.w;
            const float4 vu = *reinterpret_cast<const float4*>(
                Wu + (size_t)(colBase + r) * Kd + k0 + c4 * 4);
            Bus[c4 * 4 + 0][r] = vu.x;
            Bus[c4 * 4 + 1][r] = vu.y;
            Bus[c4 * 4 + 2][r] = vu.z;
            Bus[c4 * 4 + 3][r] = vu.w;
        }
        __syncthreads();
#pragma unroll
        for (int kk = 0; kk < 16; kk++) {
            // 8 A rows as 4 packed row-pairs (contiguous in smem)
            const unsigned long long* ap =
                reinterpret_cast<const unsigned long long*>(&As[kk][ty * 8]);
            unsigned long long a2[4] = {ap[0], ap[1], ap[2], ap[3]};
            float4 bg = *reinterpret_cast<const float4*>(&Bgs[kk][tx * 4]);
            float4 bu = *reinterpret_cast<const float4*>(&Bus[kk][tx * 4]);
            unsigned long long bg2[4] = {pk2(bg.x), pk2(bg.y), pk2(bg.z), pk2(bg.w)};
            unsigned long long bu2[4] = {pk2(bu.x), pk2(bu.y), pk2(bu.z), pk2(bu.w)};
#pragma unroll
            for (int p = 0; p < 4; p++) {
#pragma unroll
                for (int j = 0; j < 4; j++) {
                    fma2(accg2[p][j], a2[p], bg2[j]);
                    fma2(accu2[p][j], a2[p], bu2[j]);
                }
            }
        }
        __syncthreads();
    }

    // epilogue: silu(g) * u -> g_hdn  (row-pair p covers rows ty*8+2p, +1)
#pragma unroll
    for (int p = 0; p < 4; p++) {
        float2 g2[4], u2[4];
#pragma unroll
        for (int j = 0; j < 4; j++) { g2[j] = up2(accg2[p][j]); u2[j] = up2(accu2[p][j]); }
        int growL = rowBase + ty * 8 + 2 * p;
        if (growL < rows) {
            float4 hv;
            hv.x = (g2[0].x / (1.f + expf(-g2[0].x))) * u2[0].x;
            hv.y = (g2[1].x / (1.f + expf(-g2[1].x))) * u2[1].x;
            hv.z = (g2[2].x / (1.f + expf(-g2[2].x))) * u2[2].x;
            hv.w = (g2[3].x / (1.f + expf(-g2[3].x))) * u2[3].x;
            *reinterpret_cast<float4*>(
                &g_hdn[(size_t)(base + growL) * N + colBase + tx * 4]) = hv;
        }
        int growH = growL + 1;
        if (growH < rows) {
            float4 hv;
            hv.x = (g2[0].y / (1.f + expf(-g2[0].y))) * u2[0].y;
            hv.y = (g2[1].y / (1.f + expf(-g2[1].y))) * u2[1].y;
            hv.z = (g2[2].y / (1.f + expf(-g2[2].y))) * u2[2].y;
            hv.w = (g2[3].y / (1.f + expf(-g2[3].y))) * u2[3].y;
            *reinterpret_cast<float4*>(
                &g_hdn[(size_t)(base + growH) * N + colBase + tx * 4]) = hv;
        }
    }
}

// ---------------------------------------------------------------------------
// Down-projection GEMM (FFMA2) + weighted atomic scatter into out.
// ---------------------------------------------------------------------------
template <int GATHER>
__global__ void __launch_bounds__(256, 2)
k_down(const float* __restrict__ Wdb,
       float* __restrict__ Out,
       int N, int Kd) {
    int rows, base;
    const float* Wd;
    if (GATHER) {
        int e = blockIdx.z;
        rows = g_cnt[e];
        base = g_off[e];
        Wd = Wdb + (size_t)e * N * Kd;
    } else {
        rows = T_TOK; base = 0; Wd = Wdb;
    }
    int rowBase = blockIdx.y * 128;
    if (rowBase >= rows) return;
    int colBase = blockIdx.x * 64;

    __shared__ float As[16][132];
    __shared__ float Bs[16][68];

    int tid = threadIdx.x;
    int tx = tid & 15;
    int ty = tid >> 4;

    unsigned long long acc2[4][4];
#pragma unroll
    for (int p = 0; p < 4; p++)
#pragma unroll
        for (int j = 0; j < 4; j++) acc2[p][j] = 0ULL;

    for (int k0 = 0; k0 < Kd; k0 += 16) {
#pragma unroll
        for (int i = 0; i < 2; i++) {
            int idx = tid + i * 256;
            int r = idx >> 2;
            int c4 = idx & 3;
            float4 v = make_float4(0.f, 0.f, 0.f, 0.f);
            int grow = rowBase + r;
            if (grow < rows) {
                v = *reinterpret_cast<const float4*>(
                    &g_hdn[(size_t)(base + grow) * Kd + k0 + c4 * 4]);
            }
            As[c4 * 4 + 0][r] = v.x;
            As[c4 * 4 + 1][r] = v.y;
            As[c4 * 4 + 2][r] = v.z;
            As[c4 * 4 + 3][r] = v.w;
        }
        {
            int r = tid >> 2;
            int c4 = tid & 3;
            const float4 vb = *reinterpret_cast<const float4*>(
                Wd + (size_t)(colBase + r) * Kd + k0 + c4 * 4);
            Bs[c4 * 4 + 0][r] = vb.x;
            Bs[c4 * 4 + 1][r] = vb.y;
            Bs[c4 * 4 + 2][r] = vb.z;
            Bs[c4 * 4 + 3][r] = vb.w;
        }
        __syncthreads();
#pragma unroll
        for (int kk = 0; kk < 16; kk++) {
            const unsigned long long* ap =
                reinterpret_cast<const unsigned long long*>(&As[kk][ty * 8]);
            unsigned long long a2[4] = {ap[0], ap[1], ap[2], ap[3]};
            float4 bv = *reinterpret_cast<const float4*>(&Bs[kk][tx * 4]);
            unsigned long long b2[4] = {pk2(bv.x), pk2(bv.y), pk2(bv.z), pk2(bv.w)};
#pragma unroll
            for (int p = 0; p < 4; p++)
#pragma unroll
                for (int j = 0; j < 4; j++)
                    fma2(acc2[p][j], a2[p], b2[j]);
        }
        __syncthreads();
    }

#pragma unroll
    for (int p = 0; p < 4; p++) {
        float2 c2[4];
#pragma unroll
        for (int j = 0; j < 4; j++) c2[j] = up2(acc2[p][j]);
#pragma unroll
        for (int half = 0; half < 2; half++) {
            int grow = rowBase + ty * 8 + 2 * p + half;
            if (grow >= rows) continue;
            int tok;
            float w;
            if (GATHER) { tok = g_rowtok[base + grow]; w = g_roww[base + grow]; }
            else        { tok = grow;                  w = g_sgate[grow]; }
            float* op = Out + (size_t)tok * N + colBase + tx * 4;
            float v0 = half ? c2[0].y : c2[0].x;
            float v1 = half ? c2[1].y : c2[1].x;
            float v2 = half ? c2[2].y : c2[2].x;
            float v3 = half ? c2[3].y : c2[3].x;
            atomicAdd(op + 0, w * v0);
            atomicAdd(op + 1, w * v1);
            atomicAdd(op + 2, w * v2);
            atomicAdd(op + 3, w * v3);
        }
    }
}

// ---------------------------------------------------------------------------
extern "C" void kernel_launch(void* const* d_in, const int* in_sizes, int n_in,
                              void* d_out, int out_size) {
    const float* x    = (const float*)d_in[0];  // [B,S,H]
    const float* gw   = (const float*)d_in[1];  // [E,H]
    const float* egw  = (const float*)d_in[2];  // [E,FE,H]
    const float* euw  = (const float*)d_in[3];  // [E,FE,H]
    const float* edw  = (const float*)d_in[4];  // [E,H,FE]
    const float* sgw  = (const float*)d_in[5];  // [FS,H]
    const float* suw  = (const float*)d_in[6];  // [FS,H]
    const float* sdw  = (const float*)d_in[7];  // [H,FS]
    const float* segw = (const float*)d_in[8];  // [1,H]
    float* out = (float*)d_out;

    cudaMemsetAsync(out, 0, sizeof(float) * (size_t)out_size, 0);
    k_init<<<1, 32>>>();
    k_router<<<T_TOK / 8, 256>>>(x, gw, segw);
    k_offsets<<<1, 32>>>();
    k_assign<<<T_TOK / 256, 256>>>();

    // Expert path: fused gate+up (gathered), then down + weighted scatter
    k_gateup<1><<<dim3(FE / 64, T_TOK / 128, NEXP), 256>>>(x, egw, euw, FE, HDIM);
    k_down<1><<<dim3(HDIM / 64, T_TOK / 128, NEXP), 256>>>(edw, out, HDIM, FE);

    // Shared expert path (reuses g_hdn)
    k_gateup<0><<<dim3(FS / 64, T_TOK / 128, 1), 256>>>(x, sgw, suw, FS, HDIM);
    k_down<0><<<dim3(HDIM / 64, T_TOK / 128, 1), 256>>>(sdw, out, HDIM, FS);
}

// round 12
// speedup vs baseline: 1.0818x; 1.0486x over previous
#include <cuda_runtime.h>
#include <cstdint>
#include <math.h>

#define T_TOK 4096
#define HDIM  2048
#define NEXP  16
#define TOPK  4
#define FE    1408
#define FS    5632

// Scratch: max(T*K*FE, T*FS) floats -- both exactly 23,068,672 (92.3 MB)
__device__ float g_hdn[23068672];
__device__ int   g_selE[T_TOK * TOPK];
__device__ float g_selW[T_TOK * TOPK];
__device__ int   g_rowtok[T_TOK * TOPK];
__device__ float g_roww[T_TOK * TOPK];
__device__ float g_sgate[T_TOK];
__device__ int   g_cnt[NEXP];
__device__ int   g_off[NEXP + 1];
__device__ int   g_cur[NEXP];

// ---------------------------------------------------------------------------
__global__ void k_init() {
    if (threadIdx.x < NEXP) g_cnt[threadIdx.x] = 0;
}

// ---------------------------------------------------------------------------
// Router: one warp per token (proven)
// ---------------------------------------------------------------------------
__global__ void k_router(const float* __restrict__ X,
                         const float* __restrict__ GW,
                         const float* __restrict__ SEGW) {
    int warp = (blockIdx.x * blockDim.x + threadIdx.x) >> 5;
    int lane = threadIdx.x & 31;
    if (warp >= T_TOK) return;
    const float* xr = X + (size_t)warp * HDIM;

    float part[NEXP];
    float ps = 0.f;
#pragma unroll
    for (int e = 0; e < NEXP; e++) part[e] = 0.f;

    for (int h = lane; h < HDIM; h += 32) {
        float xv = xr[h];
#pragma unroll
        for (int e = 0; e < NEXP; e++) part[e] += xv * GW[e * HDIM + h];
        ps += xv * SEGW[h];
    }
#pragma unroll
    for (int e = 0; e < NEXP; e++) {
#pragma unroll
        for (int o = 16; o > 0; o >>= 1)
            part[e] += __shfl_down_sync(0xffffffffu, part[e], o);
    }
#pragma unroll
    for (int o = 16; o > 0; o >>= 1)
        ps += __shfl_down_sync(0xffffffffu, ps, o);

    if (lane == 0) {
        float m = part[0];
#pragma unroll
        for (int e = 1; e < NEXP; e++) m = fmaxf(m, part[e]);
        float r[NEXP];
        float den = 0.f;
#pragma unroll
        for (int e = 0; e < NEXP; e++) { r[e] = expf(part[e] - m); den += r[e]; }
        float inv = 1.f / den;
#pragma unroll
        for (int e = 0; e < NEXP; e++) r[e] *= inv;

        int   se[TOPK];
        float sw[TOPK];
        float s4 = 0.f;
#pragma unroll
        for (int k = 0; k < TOPK; k++) {
            int bi = 0; float bv = -1.f;
#pragma unroll
            for (int e = 0; e < NEXP; e++)
                if (r[e] > bv) { bv = r[e]; bi = e; }
            se[k] = bi; sw[k] = bv; s4 += bv;
            r[bi] = -2.f;
        }
        float invs4 = 1.f / s4;
#pragma unroll
        for (int k = 0; k < TOPK; k++) {
            g_selE[warp * TOPK + k] = se[k];
            g_selW[warp * TOPK + k] = sw[k] * invs4;
            atomicAdd(&g_cnt[se[k]], 1);
        }
        g_sgate[warp] = 1.f / (1.f + expf(-ps));
    }
}

// ---------------------------------------------------------------------------
__global__ void k_offsets() {
    if (threadIdx.x == 0) {
        int acc = 0;
        for (int e = 0; e < NEXP; e++) {
            g_off[e] = acc;
            acc += g_cnt[e];
            g_cur[e] = 0;
        }
        g_off[NEXP] = acc;
    }
}

// ---------------------------------------------------------------------------
__global__ void k_assign() {
    int t = blockIdx.x * blockDim.x + threadIdx.x;
    if (t >= T_TOK) return;
#pragma unroll
    for (int k = 0; k < TOPK; k++) {
        int e = g_selE[t * TOPK + k];
        int slot = atomicAdd(&g_cur[e], 1);
        int pos = g_off[e] + slot;
        g_rowtok[pos] = t;
        g_roww[pos] = g_selW[t * TOPK + k];
    }
}

// ---------------------------------------------------------------------------
// Packed fp32x2 helpers (fma.rn.f32x2: 2 exact fp32 FMAs / instr; proven R11)
// ---------------------------------------------------------------------------
__device__ __forceinline__ unsigned long long pk2(float x) {
    unsigned long long r;
    asm("mov.b64 %0, {%1, %1};" : "=l"(r) : "f"(x));
    return r;
}
__device__ __forceinline__ void fma2(unsigned long long& d,
                                     unsigned long long a,
                                     unsigned long long b) {
    asm("fma.rn.f32x2 %0, %1, %2, %0;" : "+l"(d) : "l"(a), "l"(b));
}
__device__ __forceinline__ float2 up2(unsigned long long v) {
    float lo, hi;
    asm("mov.b64 {%0, %1}, %2;" : "=f"(lo), "=f"(hi) : "l"(v));
    return make_float2(lo, hi);
}

// ---------------------------------------------------------------------------
// Fused gate+up GEMM, 128(M) x 128(B-combined: 64 gate + 64 up cols),
// BK=16, double-buffered smem, 1 barrier/iter, FFMA2.
// Per thread: 4 row-pairs x (4 gate + 4 up) cols.
// GATHER=1: per-expert gathered rows (z=expert); GATHER=0: shared expert.
// ---------------------------------------------------------------------------
template <int GATHER>
__global__ void __launch_bounds__(256, 2)
k_gateup(const float* __restrict__ X,
         const float* __restrict__ Wgb,
         const float* __restrict__ Wub,
         int N, int Kd) {
    int rows, base;
    const float* Wg;
    const float* Wu;
    if (GATHER) {
        int e = blockIdx.z;
        rows = g_cnt[e];
        base = g_off[e];
        size_t wo = (size_t)e * N * Kd;
        Wg = Wgb + wo; Wu = Wub + wo;
    } else {
        rows = T_TOK; base = 0; Wg = Wgb; Wu = Wub;
    }
    int rowBase = blockIdx.y * 128;
    if (rowBase >= rows) return;
    int colBase = blockIdx.x * 64;   // 64 logical cols (each has gate+up)

    __shared__ float As[2][16][132];
    __shared__ float Bs[2][16][132];   // rows 0-63: Wg cols, 64-127: Wu cols

    const int tid = threadIdx.x;
    const int tx = tid & 15;   // 4 logical cols
    const int ty = tid >> 4;   // 8 rows (4 pairs)

    // loader mapping: 2 float4 per thread per tile for A and for B-combined
    int ar[2], ac[2];
    const float* aptr[2];
    bool aval[2];
    const float* bptr[2];
    int br[2], bc[2];
#pragma unroll
    for (int i = 0; i < 2; i++) {
        int idx = tid + i * 256;
        ar[i] = idx >> 2;
        ac[i] = (idx & 3) * 4;
        int grow = rowBase + ar[i];
        aval[i] = grow < rows;
        if (GATHER) {
            int tok = aval[i] ? g_rowtok[base + grow] : 0;
            aptr[i] = X + (size_t)tok * Kd + ac[i];
        } else {
            aptr[i] = X + (size_t)(aval[i] ? grow : 0) * Kd + ac[i];
        }
        br[i] = idx >> 2;
        bc[i] = (idx & 3) * 4;
        if (br[i] < 64)
            bptr[i] = Wg + (size_t)(colBase + br[i]) * Kd + bc[i];
        else
            bptr[i] = Wu + (size_t)(colBase + br[i] - 64) * Kd + bc[i];
    }

    unsigned long long accg2[4][4];
    unsigned long long accu2[4][4];
#pragma unroll
    for (int p = 0; p < 4; p++)
#pragma unroll
        for (int j = 0; j < 4; j++) { accg2[p][j] = 0ULL; accu2[p][j] = 0ULL; }

    const int KT = Kd >> 4;

    // prologue: tile 0
    float4 sva[2], svb[2];
#pragma unroll
    for (int i = 0; i < 2; i++) {
        sva[i] = aval[i] ? *reinterpret_cast<const float4*>(aptr[i])
                         : make_float4(0.f, 0.f, 0.f, 0.f);
        svb[i] = *reinterpret_cast<const float4*>(bptr[i]);
    }
#pragma unroll
    for (int i = 0; i < 2; i++) {
        As[0][ac[i] + 0][ar[i]] = sva[i].x;
        As[0][ac[i] + 1][ar[i]] = sva[i].y;
        As[0][ac[i] + 2][ar[i]] = sva[i].z;
        As[0][ac[i] + 3][ar[i]] = sva[i].w;
        Bs[0][bc[i] + 0][br[i]] = svb[i].x;
        Bs[0][bc[i] + 1][br[i]] = svb[i].y;
        Bs[0][bc[i] + 2][br[i]] = svb[i].z;
        Bs[0][bc[i] + 3][br[i]] = svb[i].w;
    }
    __syncthreads();

    for (int kt = 0; kt < KT; kt++) {
        int cur = kt & 1;
        // issue next tile's global loads (latency overlaps compute)
        if (kt + 1 < KT) {
            int k0 = (kt + 1) << 4;
#pragma unroll
            for (int i = 0; i < 2; i++) {
                sva[i] = aval[i] ? *reinterpret_cast<const float4*>(aptr[i] + k0)
                                 : make_float4(0.f, 0.f, 0.f, 0.f);
                svb[i] = *reinterpret_cast<const float4*>(bptr[i] + k0);
            }
        }
        // compute on current buffer
#pragma unroll
        for (int kk = 0; kk < 16; kk++) {
            const unsigned long long* ap =
                reinterpret_cast<const unsigned long long*>(&As[cur][kk][ty * 8]);
            unsigned long long a2[4] = {ap[0], ap[1], ap[2], ap[3]};
            float4 bg = *reinterpret_cast<const float4*>(&Bs[cur][kk][tx * 4]);
            float4 bu = *reinterpret_cast<const float4*>(&Bs[cur][kk][64 + tx * 4]);
            unsigned long long bg2[4] = {pk2(bg.x), pk2(bg.y), pk2(bg.z), pk2(bg.w)};
            unsigned long long bu2[4] = {pk2(bu.x), pk2(bu.y), pk2(bu.z), pk2(bu.w)};
#pragma unroll
            for (int p = 0; p < 4; p++) {
#pragma unroll
                for (int j = 0; j < 4; j++) {
                    fma2(accg2[p][j], a2[p], bg2[j]);
                    fma2(accu2[p][j], a2[p], bu2[j]);
                }
            }
        }
        // stage next tile into the other buffer
        if (kt + 1 < KT) {
            int nxt = cur ^ 1;
#pragma unroll
            for (int i = 0; i < 2; i++) {
                As[nxt][ac[i] + 0][ar[i]] = sva[i].x;
                As[nxt][ac[i] + 1][ar[i]] = sva[i].y;
                As[nxt][ac[i] + 2][ar[i]] = sva[i].z;
                As[nxt][ac[i] + 3][ar[i]] = sva[i].w;
                Bs[nxt][bc[i] + 0][br[i]] = svb[i].x;
                Bs[nxt][bc[i] + 1][br[i]] = svb[i].y;
                Bs[nxt][bc[i] + 2][br[i]] = svb[i].z;
                Bs[nxt][bc[i] + 3][br[i]] = svb[i].w;
            }
        }
        __syncthreads();
    }

    // epilogue: silu(g)*u -> g_hdn (row-pair p covers rows ty*8+2p, +1)
#pragma unroll
    for (int p = 0; p < 4; p++) {
        float2 g2[4], u2[4];
#pragma unroll
        for (int j = 0; j < 4; j++) { g2[j] = up2(accg2[p][j]); u2[j] = up2(accu2[p][j]); }
        int growL = rowBase + ty * 8 + 2 * p;
        if (growL < rows) {
            float4 hv;
            hv.x = (g2[0].x / (1.f + expf(-g2[0].x))) * u2[0].x;
            hv.y = (g2[1].x / (1.f + expf(-g2[1].x))) * u2[1].x;
            hv.z = (g2[2].x / (1.f + expf(-g2[2].x))) * u2[2].x;
            hv.w = (g2[3].x / (1.f + expf(-g2[3].x))) * u2[3].x;
            *reinterpret_cast<float4*>(
                &g_hdn[(size_t)(base + growL) * N + colBase + tx * 4]) = hv;
        }
        int growH = growL + 1;
        if (growH < rows) {
            float4 hv;
            hv.x = (g2[0].y / (1.f + expf(-g2[0].y))) * u2[0].y;
            hv.y = (g2[1].y / (1.f + expf(-g2[1].y))) * u2[1].y;
            hv.z = (g2[2].y / (1.f + expf(-g2[2].y))) * u2[2].y;
            hv.w = (g2[3].y / (1.f + expf(-g2[3].y))) * u2[3].y;
            *reinterpret_cast<float4*>(
                &g_hdn[(size_t)(base + growH) * N + colBase + tx * 4]) = hv;
        }
    }
}

// ---------------------------------------------------------------------------
// Down GEMM, 128(M) x 128(N), BK=16, double-buffered, FFMA2,
// weighted atomic scatter. Per thread: 4 row-pairs x 8 cols (tx*4, 64+tx*4).
// ---------------------------------------------------------------------------
template <int GATHER>
__global__ void __launch_bounds__(256, 2)
k_down(const float* __restrict__ Wdb,
       float* __restrict__ Out,
       int N, int Kd) {
    int rows, base;
    const float* Wd;
    if (GATHER) {
        int e = blockIdx.z;
        rows = g_cnt[e];
        base = g_off[e];
        Wd = Wdb + (size_t)e * N * Kd;
    } else {
        rows = T_TOK; base = 0; Wd = Wdb;
    }
    int rowBase = blockIdx.y * 128;
    if (rowBase >= rows) return;
    int colBase = blockIdx.x * 128;

    __shared__ float As[2][16][132];
    __shared__ float Bs[2][16][132];

    const int tid = threadIdx.x;
    const int tx = tid & 15;
    const int ty = tid >> 4;

    int ar[2], ac[2];
    const float* aptr[2];
    bool aval[2];
    const float* bptr[2];
    int br[2], bc[2];
#pragma unroll
    for (int i = 0; i < 2; i++) {
        int idx = tid + i * 256;
        ar[i] = idx >> 2;
        ac[i] = (idx & 3) * 4;
        int grow = rowBase + ar[i];
        aval[i] = grow < rows;
        aptr[i] = g_hdn + (size_t)(base + (aval[i] ? grow : 0)) * Kd + ac[i];
        br[i] = idx >> 2;
        bc[i] = (idx & 3) * 4;
        bptr[i] = Wd + (size_t)(colBase + br[i]) * Kd + bc[i];
    }

    unsigned long long acc2[4][8];
#pragma unroll
    for (int p = 0; p < 4; p++)
#pragma unroll
        for (int j = 0; j < 8; j++) acc2[p][j] = 0ULL;

    const int KT = Kd >> 4;

    float4 sva[2], svb[2];
#pragma unroll
    for (int i = 0; i < 2; i++) {
        sva[i] = aval[i] ? *reinterpret_cast<const float4*>(aptr[i])
                         : make_float4(0.f, 0.f, 0.f, 0.f);
        svb[i] = *reinterpret_cast<const float4*>(bptr[i]);
    }
#pragma unroll
    for (int i = 0; i < 2; i++) {
        As[0][ac[i] + 0][ar[i]] = sva[i].x;
        As[0][ac[i] + 1][ar[i]] = sva[i].y;
        As[0][ac[i] + 2][ar[i]] = sva[i].z;
        As[0][ac[i] + 3][ar[i]] = sva[i].w;
        Bs[0][bc[i] + 0][br[i]] = svb[i].x;
        Bs[0][bc[i] + 1][br[i]] = svb[i].y;
        Bs[0][bc[i] + 2][br[i]] = svb[i].z;
        Bs[0][bc[i] + 3][br[i]] = svb[i].w;
    }
    __syncthreads();

    for (int kt = 0; kt < KT; kt++) {
        int cur = kt & 1;
        if (kt + 1 < KT) {
            int k0 = (kt + 1) << 4;
#pragma unroll
            for (int i = 0; i < 2; i++) {
                sva[i] = aval[i] ? *reinterpret_cast<const float4*>(aptr[i] + k0)
                                 : make_float4(0.f, 0.f, 0.f, 0.f);
                svb[i] = *reinterpret_cast<const float4*>(bptr[i] + k0);
            }
        }
#pragma unroll
        for (int kk = 0; kk < 16; kk++) {
            const unsigned long long* ap =
                reinterpret_cast<const unsigned long long*>(&As[cur][kk][ty * 8]);
            unsigned long long a2[4] = {ap[0], ap[1], ap[2], ap[3]};
            float4 b0 = *reinterpret_cast<const float4*>(&Bs[cur][kk][tx * 4]);
            float4 b1 = *reinterpret_cast<const float4*>(&Bs[cur][kk][64 + tx * 4]);
            unsigned long long b2[8] = {pk2(b0.x), pk2(b0.y), pk2(b0.z), pk2(b0.w),
                                        pk2(b1.x), pk2(b1.y), pk2(b1.z), pk2(b1.w)};
#pragma unroll
            for (int p = 0; p < 4; p++)
#pragma unroll
                for (int j = 0; j < 8; j++)
                    fma2(acc2[p][j], a2[p], b2[j]);
        }
        if (kt + 1 < KT) {
            int nxt = cur ^ 1;
#pragma unroll
            for (int i = 0; i < 2; i++) {
                As[nxt][ac[i] + 0][ar[i]] = sva[i].x;
                As[nxt][ac[i] + 1][ar[i]] = sva[i].y;
                As[nxt][ac[i] + 2][ar[i]] = sva[i].z;
                As[nxt][ac[i] + 3][ar[i]] = sva[i].w;
                Bs[nxt][bc[i] + 0][br[i]] = svb[i].x;
                Bs[nxt][bc[i] + 1][br[i]] = svb[i].y;
                Bs[nxt][bc[i] + 2][br[i]] = svb[i].z;
                Bs[nxt][bc[i] + 3][br[i]] = svb[i].w;
            }
        }
        __syncthreads();
    }

    // epilogue: weighted atomic scatter (guarded)
#pragma unroll
    for (int p = 0; p < 4; p++) {
        float2 c2[8];
#pragma unroll
        for (int j = 0; j < 8; j++) c2[j] = up2(acc2[p][j]);
#pragma unroll
        for (int half = 0; half < 2; half++) {
            int grow = rowBase + ty * 8 + 2 * p + half;
            if (grow >= rows) continue;
            int tok;
            float w;
            if (GATHER) { tok = g_rowtok[base + grow]; w = g_roww[base + grow]; }
            else        { tok = grow;                  w = g_sgate[grow]; }
            float* op0 = Out + (size_t)tok * N + colBase + tx * 4;
            float* op1 = op0 + 64;
#pragma unroll
            for (int j = 0; j < 4; j++) {
                float v0 = half ? c2[j].y : c2[j].x;
                float v1 = half ? c2[j + 4].y : c2[j + 4].x;
                atomicAdd(op0 + j, w * v0);
                atomicAdd(op1 + j, w * v1);
            }
        }
    }
}

// ---------------------------------------------------------------------------
extern "C" void kernel_launch(void* const* d_in, const int* in_sizes, int n_in,
                              void* d_out, int out_size) {
    const float* x    = (const float*)d_in[0];  // [B,S,H]
    const float* gw   = (const float*)d_in[1];  // [E,H]
    const float* egw  = (const float*)d_in[2];  // [E,FE,H]
    const float* euw  = (const float*)d_in[3];  // [E,FE,H]
    const float* edw  = (const float*)d_in[4];  // [E,H,FE]
    const float* sgw  = (const float*)d_in[5];  // [FS,H]
    const float* suw  = (const float*)d_in[6];  // [FS,H]
    const float* sdw  = (const float*)d_in[7];  // [H,FS]
    const float* segw = (const float*)d_in[8];  // [1,H]
    float* out = (float*)d_out;

    cudaMemsetAsync(out, 0, sizeof(float) * (size_t)out_size, 0);
    k_init<<<1, 32>>>();
    k_router<<<T_TOK / 8, 256>>>(x, gw, segw);
    k_offsets<<<1, 32>>>();
    k_assign<<<T_TOK / 256, 256>>>();

    // Expert path: fused gate+up (gathered), then down + weighted scatter
    k_gateup<1><<<dim3(FE / 64, T_TOK / 128, NEXP), 256>>>(x, egw, euw, FE, HDIM);
    k_down<1><<<dim3(HDIM / 128, T_TOK / 128, NEXP), 256>>>(edw, out, HDIM, FE);

    // Shared expert path (reuses g_hdn)
    k_gateup<0><<<dim3(FS / 64, T_TOK / 128, 1), 256>>>(x, sgw, suw, FS, HDIM);
    k_down<0><<<dim3(HDIM / 128, T_TOK / 128, 1), 256>>>(sdw, out, HDIM, FS);
}

// round 13
// speedup vs baseline: 1.1621x; 1.0742x over previous
#include <cuda_runtime.h>
#include <cstdint>
#include <math.h>

#define T_TOK 4096
#define HDIM  2048
#define NEXP  16
#define TOPK  4
#define FE    1408
#define FS    5632

// Scratch: max(T*K*FE, T*FS) floats -- both exactly 23,068,672 (92.3 MB)
__device__ float g_hdn[23068672];
__device__ int   g_selE[T_TOK * TOPK];
__device__ float g_selW[T_TOK * TOPK];
__device__ int   g_rowtok[T_TOK * TOPK];
__device__ float g_roww[T_TOK * TOPK];
__device__ float g_sgate[T_TOK];
__device__ int   g_cnt[NEXP];
__device__ int   g_off[NEXP + 1];
__device__ int   g_cur[NEXP];

// ---------------------------------------------------------------------------
__global__ void k_init() {
    if (threadIdx.x < NEXP) g_cnt[threadIdx.x] = 0;
}

// ---------------------------------------------------------------------------
// Router: one warp per token (proven)
// ---------------------------------------------------------------------------
__global__ void k_router(const float* __restrict__ X,
                         const float* __restrict__ GW,
                         const float* __restrict__ SEGW) {
    int warp = (blockIdx.x * blockDim.x + threadIdx.x) >> 5;
    int lane = threadIdx.x & 31;
    if (warp >= T_TOK) return;
    const float* xr = X + (size_t)warp * HDIM;

    float part[NEXP];
    float ps = 0.f;
#pragma unroll
    for (int e = 0; e < NEXP; e++) part[e] = 0.f;

    for (int h = lane; h < HDIM; h += 32) {
        float xv = xr[h];
#pragma unroll
        for (int e = 0; e < NEXP; e++) part[e] += xv * GW[e * HDIM + h];
        ps += xv * SEGW[h];
    }
#pragma unroll
    for (int e = 0; e < NEXP; e++) {
#pragma unroll
        for (int o = 16; o > 0; o >>= 1)
            part[e] += __shfl_down_sync(0xffffffffu, part[e], o);
    }
#pragma unroll
    for (int o = 16; o > 0; o >>= 1)
        ps += __shfl_down_sync(0xffffffffu, ps, o);

    if (lane == 0) {
        float m = part[0];
#pragma unroll
        for (int e = 1; e < NEXP; e++) m = fmaxf(m, part[e]);
        float r[NEXP];
        float den = 0.f;
#pragma unroll
        for (int e = 0; e < NEXP; e++) { r[e] = expf(part[e] - m); den += r[e]; }
        float inv = 1.f / den;
#pragma unroll
        for (int e = 0; e < NEXP; e++) r[e] *= inv;

        int   se[TOPK];
        float sw[TOPK];
        float s4 = 0.f;
#pragma unroll
        for (int k = 0; k < TOPK; k++) {
            int bi = 0; float bv = -1.f;
#pragma unroll
            for (int e = 0; e < NEXP; e++)
                if (r[e] > bv) { bv = r[e]; bi = e; }
            se[k] = bi; sw[k] = bv; s4 += bv;
            r[bi] = -2.f;
        }
        float invs4 = 1.f / s4;
#pragma unroll
        for (int k = 0; k < TOPK; k++) {
            g_selE[warp * TOPK + k] = se[k];
            g_selW[warp * TOPK + k] = sw[k] * invs4;
            atomicAdd(&g_cnt[se[k]], 1);
        }
        g_sgate[warp] = 1.f / (1.f + expf(-ps));
    }
}

// ---------------------------------------------------------------------------
__global__ void k_offsets() {
    if (threadIdx.x == 0) {
        int acc = 0;
        for (int e = 0; e < NEXP; e++) {
            g_off[e] = acc;
            acc += g_cnt[e];
            g_cur[e] = 0;
        }
        g_off[NEXP] = acc;
    }
}

// ---------------------------------------------------------------------------
__global__ void k_assign() {
    int t = blockIdx.x * blockDim.x + threadIdx.x;
    if (t >= T_TOK) return;
#pragma unroll
    for (int k = 0; k < TOPK; k++) {
        int e = g_selE[t * TOPK + k];
        int slot = atomicAdd(&g_cur[e], 1);
        int pos = g_off[e] + slot;
        g_rowtok[pos] = t;
        g_roww[pos] = g_selW[t * TOPK + k];
    }
}

// ---------------------------------------------------------------------------
// Packed fp32x2 helpers (proven R11/R12)
// ---------------------------------------------------------------------------
__device__ __forceinline__ unsigned long long pk2(float x) {
    unsigned long long r;
    asm("mov.b64 %0, {%1, %1};" : "=l"(r) : "f"(x));
    return r;
}
__device__ __forceinline__ void fma2(unsigned long long& d,
                                     unsigned long long a,
                                     unsigned long long b) {
    asm("fma.rn.f32x2 %0, %1, %2, %0;" : "+l"(d) : "l"(a), "l"(b));
}
__device__ __forceinline__ float2 up2(unsigned long long v) {
    float lo, hi;
    asm("mov.b64 {%0, %1}, %2;" : "=f"(lo), "=f"(hi) : "l"(v));
    return make_float2(lo, hi);
}

// ---------------------------------------------------------------------------
// Fused gate+up GEMM, 128(M) x 64-logical(N) (gate+up combined = 128 B rows),
// BK=16, 128 threads (8 ty x 16 tx), per-thread 16 rows x (4g+4u) cols.
// Register-staged double buffering, one barrier/iter, FFMA2.
// smem bytes/FLOP: 0.375 (vs 0.5 before).
// ---------------------------------------------------------------------------
template <int GATHER>
__global__ void __launch_bounds__(128, 2)
k_gateup(const float* __restrict__ X,
         const float* __restrict__ Wgb,
         const float* __restrict__ Wub,
         int N, int Kd) {
    int rows, base;
    const float* Wg;
    const float* Wu;
    if (GATHER) {
        int e = blockIdx.z;
        rows = g_cnt[e];
        base = g_off[e];
        size_t wo = (size_t)e * N * Kd;
        Wg = Wgb + wo; Wu = Wub + wo;
    } else {
        rows = T_TOK; base = 0; Wg = Wgb; Wu = Wub;
    }
    int rowBase = blockIdx.y * 128;
    if (rowBase >= rows) return;
    int colBase = blockIdx.x * 64;   // 64 logical cols (each gate+up)

    __shared__ float As[2][16][132];
    __shared__ float Bs[2][16][132];   // rows 0-63: Wg cols, 64-127: Wu cols

    const int tid = threadIdx.x;
    const int tx = tid & 15;   // 4 logical cols
    const int ty = tid >> 4;   // 16 rows (8 pairs)

    // loaders: 4 float4 per thread per tile for A and for B-combined
    int ar[4], ac[4];
    const float* aptr[4];
    bool aval[4];
    const float* bptr[4];
    int br[4], bc[4];
#pragma unroll
    for (int i = 0; i < 4; i++) {
        int idx = tid + i * 128;
        ar[i] = idx >> 2;
        ac[i] = (idx & 3) * 4;
        int grow = rowBase + ar[i];
        aval[i] = grow < rows;
        if (GATHER) {
            int tok = aval[i] ? g_rowtok[base + grow] : 0;
            aptr[i] = X + (size_t)tok * Kd + ac[i];
        } else {
            aptr[i] = X + (size_t)(aval[i] ? grow : 0) * Kd + ac[i];
        }
        br[i] = idx >> 2;
        bc[i] = (idx & 3) * 4;
        if (br[i] < 64)
            bptr[i] = Wg + (size_t)(colBase + br[i]) * Kd + bc[i];
        else
            bptr[i] = Wu + (size_t)(colBase + br[i] - 64) * Kd + bc[i];
    }

    unsigned long long accg2[8][4];
    unsigned long long accu2[8][4];
#pragma unroll
    for (int p = 0; p < 8; p++)
#pragma unroll
        for (int j = 0; j < 4; j++) { accg2[p][j] = 0ULL; accu2[p][j] = 0ULL; }

    const int KT = Kd >> 4;

    float4 sva[4], svb[4];
#pragma unroll
    for (int i = 0; i < 4; i++) {
        sva[i] = aval[i] ? *reinterpret_cast<const float4*>(aptr[i])
                         : make_float4(0.f, 0.f, 0.f, 0.f);
        svb[i] = *reinterpret_cast<const float4*>(bptr[i]);
    }
#pragma unroll
    for (int i = 0; i < 4; i++) {
        As[0][ac[i] + 0][ar[i]] = sva[i].x;
        As[0][ac[i] + 1][ar[i]] = sva[i].y;
        As[0][ac[i] + 2][ar[i]] = sva[i].z;
        As[0][ac[i] + 3][ar[i]] = sva[i].w;
        Bs[0][bc[i] + 0][br[i]] = svb[i].x;
        Bs[0][bc[i] + 1][br[i]] = svb[i].y;
        Bs[0][bc[i] + 2][br[i]] = svb[i].z;
        Bs[0][bc[i] + 3][br[i]] = svb[i].w;
    }
    __syncthreads();

    for (int kt = 0; kt < KT; kt++) {
        int cur = kt & 1;
        if (kt + 1 < KT) {
            int k0 = (kt + 1) << 4;
#pragma unroll
            for (int i = 0; i < 4; i++) {
                sva[i] = aval[i] ? *reinterpret_cast<const float4*>(aptr[i] + k0)
                                 : make_float4(0.f, 0.f, 0.f, 0.f);
                svb[i] = *reinterpret_cast<const float4*>(bptr[i] + k0);
            }
        }
#pragma unroll
        for (int kk = 0; kk < 16; kk++) {
            // 16 A rows as 8 packed pairs: 4 x ulonglong2 (16B-aligned)
            const ulonglong2* ap =
                reinterpret_cast<const ulonglong2*>(&As[cur][kk][ty * 16]);
            ulonglong2 av0 = ap[0], av1 = ap[1], av2 = ap[2], av3 = ap[3];
            unsigned long long a2[8] = {av0.x, av0.y, av1.x, av1.y,
                                        av2.x, av2.y, av3.x, av3.y};
            float4 bg = *reinterpret_cast<const float4*>(&Bs[cur][kk][tx * 4]);
            float4 bu = *reinterpret_cast<const float4*>(&Bs[cur][kk][64 + tx * 4]);
            unsigned long long bg2[4] = {pk2(bg.x), pk2(bg.y), pk2(bg.z), pk2(bg.w)};
            unsigned long long bu2[4] = {pk2(bu.x), pk2(bu.y), pk2(bu.z), pk2(bu.w)};
#pragma unroll
            for (int p = 0; p < 8; p++) {
#pragma unroll
                for (int j = 0; j < 4; j++) {
                    fma2(accg2[p][j], a2[p], bg2[j]);
                    fma2(accu2[p][j], a2[p], bu2[j]);
                }
            }
        }
        if (kt + 1 < KT) {
            int nxt = cur ^ 1;
#pragma unroll
            for (int i = 0; i < 4; i++) {
                As[nxt][ac[i] + 0][ar[i]] = sva[i].x;
                As[nxt][ac[i] + 1][ar[i]] = sva[i].y;
                As[nxt][ac[i] + 2][ar[i]] = sva[i].z;
                As[nxt][ac[i] + 3][ar[i]] = sva[i].w;
                Bs[nxt][bc[i] + 0][br[i]] = svb[i].x;
                Bs[nxt][bc[i] + 1][br[i]] = svb[i].y;
                Bs[nxt][bc[i] + 2][br[i]] = svb[i].z;
                Bs[nxt][bc[i] + 3][br[i]] = svb[i].w;
            }
        }
        __syncthreads();
    }

    // epilogue: silu(g)*u -> g_hdn (pair p covers rows ty*16+2p, +1)
#pragma unroll
    for (int p = 0; p < 8; p++) {
        float2 g2[4], u2[4];
#pragma unroll
        for (int j = 0; j < 4; j++) { g2[j] = up2(accg2[p][j]); u2[j] = up2(accu2[p][j]); }
        int growL = rowBase + ty * 16 + 2 * p;
        if (growL < rows) {
            float4 hv;
            hv.x = (g2[0].x / (1.f + expf(-g2[0].x))) * u2[0].x;
            hv.y = (g2[1].x / (1.f + expf(-g2[1].x))) * u2[1].x;
            hv.z = (g2[2].x / (1.f + expf(-g2[2].x))) * u2[2].x;
            hv.w = (g2[3].x / (1.f + expf(-g2[3].x))) * u2[3].x;
            *reinterpret_cast<float4*>(
                &g_hdn[(size_t)(base + growL) * N + colBase + tx * 4]) = hv;
        }
        int growH = growL + 1;
        if (growH < rows) {
            float4 hv;
            hv.x = (g2[0].y / (1.f + expf(-g2[0].y))) * u2[0].y;
            hv.y = (g2[1].y / (1.f + expf(-g2[1].y))) * u2[1].y;
            hv.z = (g2[2].y / (1.f + expf(-g2[2].y))) * u2[2].y;
            hv.w = (g2[3].y / (1.f + expf(-g2[3].y))) * u2[3].y;
            *reinterpret_cast<float4*>(
                &g_hdn[(size_t)(base + growH) * N + colBase + tx * 4]) = hv;
        }
    }
}

// ---------------------------------------------------------------------------
// Down GEMM, 128(M) x 128(N), BK=16, 128 threads, per-thread 16 rows x 8 cols,
// double-buffered, FFMA2, weighted atomic scatter.
// ---------------------------------------------------------------------------
template <int GATHER>
__global__ void __launch_bounds__(128, 2)
k_down(const float* __restrict__ Wdb,
       float* __restrict__ Out,
       int N, int Kd) {
    int rows, base;
    const float* Wd;
    if (GATHER) {
        int e = blockIdx.z;
        rows = g_cnt[e];
        base = g_off[e];
        Wd = Wdb + (size_t)e * N * Kd;
    } else {
        rows = T_TOK; base = 0; Wd = Wdb;
    }
    int rowBase = blockIdx.y * 128;
    if (rowBase >= rows) return;
    int colBase = blockIdx.x * 128;

    __shared__ float As[2][16][132];
    __shared__ float Bs[2][16][132];

    const int tid = threadIdx.x;
    const int tx = tid & 15;
    const int ty = tid >> 4;

    int ar[4], ac[4];
    const float* aptr[4];
    bool aval[4];
    const float* bptr[4];
    int br[4], bc[4];
#pragma unroll
    for (int i = 0; i < 4; i++) {
        int idx = tid + i * 128;
        ar[i] = idx >> 2;
        ac[i] = (idx & 3) * 4;
        int grow = rowBase + ar[i];
        aval[i] = grow < rows;
        aptr[i] = g_hdn + (size_t)(base + (aval[i] ? grow : 0)) * Kd + ac[i];
        br[i] = idx >> 2;
        bc[i] = (idx & 3) * 4;
        bptr[i] = Wd + (size_t)(colBase + br[i]) * Kd + bc[i];
    }

    unsigned long long acc2[8][8];
#pragma unroll
    for (int p = 0; p < 8; p++)
#pragma unroll
        for (int j = 0; j < 8; j++) acc2[p][j] = 0ULL;

    const int KT = Kd >> 4;

    float4 sva[4], svb[4];
#pragma unroll
    for (int i = 0; i < 4; i++) {
        sva[i] = aval[i] ? *reinterpret_cast<const float4*>(aptr[i])
                         : make_float4(0.f, 0.f, 0.f, 0.f);
        svb[i] = *reinterpret_cast<const float4*>(bptr[i]);
    }
#pragma unroll
    for (int i = 0; i < 4; i++) {
        As[0][ac[i] + 0][ar[i]] = sva[i].x;
        As[0][ac[i] + 1][ar[i]] = sva[i].y;
        As[0][ac[i] + 2][ar[i]] = sva[i].z;
        As[0][ac[i] + 3][ar[i]] = sva[i].w;
        Bs[0][bc[i] + 0][br[i]] = svb[i].x;
        Bs[0][bc[i] + 1][br[i]] = svb[i].y;
        Bs[0][bc[i] + 2][br[i]] = svb[i].z;
        Bs[0][bc[i] + 3][br[i]] = svb[i].w;
    }
    __syncthreads();

    for (int kt = 0; kt < KT; kt++) {
        int cur = kt & 1;
        if (kt + 1 < KT) {
            int k0 = (kt + 1) << 4;
#pragma unroll
            for (int i = 0; i < 4; i++) {
                sva[i] = aval[i] ? *reinterpret_cast<const float4*>(aptr[i] + k0)
                                 : make_float4(0.f, 0.f, 0.f, 0.f);
                svb[i] = *reinterpret_cast<const float4*>(bptr[i] + k0);
            }
        }
#pragma unroll
        for (int kk = 0; kk < 16; kk++) {
            const ulonglong2* ap =
                reinterpret_cast<const ulonglong2*>(&As[cur][kk][ty * 16]);
            ulonglong2 av0 = ap[0], av1 = ap[1], av2 = ap[2], av3 = ap[3];
            unsigned long long a2[8] = {av0.x, av0.y, av1.x, av1.y,
                                        av2.x, av2.y, av3.x, av3.y};
            float4 b0 = *reinterpret_cast<const float4*>(&Bs[cur][kk][tx * 4]);
            float4 b1 = *reinterpret_cast<const float4*>(&Bs[cur][kk][64 + tx * 4]);
            unsigned long long b2[8] = {pk2(b0.x), pk2(b0.y), pk2(b0.z), pk2(b0.w),
                                        pk2(b1.x), pk2(b1.y), pk2(b1.z), pk2(b1.w)};
#pragma unroll
            for (int p = 0; p < 8; p++)
#pragma unroll
                for (int j = 0; j < 8; j++)
                    fma2(acc2[p][j], a2[p], b2[j]);
        }
        if (kt + 1 < KT) {
            int nxt = cur ^ 1;
#pragma unroll
            for (int i = 0; i < 4; i++) {
                As[nxt][ac[i] + 0][ar[i]] = sva[i].x;
                As[nxt][ac[i] + 1][ar[i]] = sva[i].y;
                As[nxt][ac[i] + 2][ar[i]] = sva[i].z;
                As[nxt][ac[i] + 3][ar[i]] = sva[i].w;
                Bs[nxt][bc[i] + 0][br[i]] = svb[i].x;
                Bs[nxt][bc[i] + 1][br[i]] = svb[i].y;
                Bs[nxt][bc[i] + 2][br[i]] = svb[i].z;
                Bs[nxt][bc[i] + 3][br[i]] = svb[i].w;
            }
        }
        __syncthreads();
    }

    // epilogue: weighted atomic scatter (guarded)
#pragma unroll
    for (int p = 0; p < 8; p++) {
        float2 c2[8];
#pragma unroll
        for (int j = 0; j < 8; j++) c2[j] = up2(acc2[p][j]);
#pragma unroll
        for (int half = 0; half < 2; half++) {
            int grow = rowBase + ty * 16 + 2 * p + half;
            if (grow >= rows) continue;
            int tok;
            float w;
            if (GATHER) { tok = g_rowtok[base + grow]; w = g_roww[base + grow]; }
            else        { tok = grow;                  w = g_sgate[grow]; }
            float* op0 = Out + (size_t)tok * N + colBase + tx * 4;
            float* op1 = op0 + 64;
#pragma unroll
            for (int j = 0; j < 4; j++) {
                float v0 = half ? c2[j].y : c2[j].x;
                float v1 = half ? c2[j + 4].y : c2[j + 4].x;
                atomicAdd(op0 + j, w * v0);
                atomicAdd(op1 + j, w * v1);
            }
        }
    }
}

// ---------------------------------------------------------------------------
extern "C" void kernel_launch(void* const* d_in, const int* in_sizes, int n_in,
                              void* d_out, int out_size) {
    const float* x    = (const float*)d_in[0];  // [B,S,H]
    const float* gw   = (const float*)d_in[1];  // [E,H]
    const float* egw  = (const float*)d_in[2];  // [E,FE,H]
    const float* euw  = (const float*)d_in[3];  // [E,FE,H]
    const float* edw  = (const float*)d_in[4];  // [E,H,FE]
    const float* sgw  = (const float*)d_in[5];  // [FS,H]
    const float* suw  = (const float*)d_in[6];  // [FS,H]
    const float* sdw  = (const float*)d_in[7];  // [H,FS]
    const float* segw = (const float*)d_in[8];  // [1,H]
    float* out = (float*)d_out;

    cudaMemsetAsync(out, 0, sizeof(float) * (size_t)out_size, 0);
    k_init<<<1, 32>>>();
    k_router<<<T_TOK / 8, 256>>>(x, gw, segw);
    k_offsets<<<1, 32>>>();
    k_assign<<<T_TOK / 256, 256>>>();

    // Expert path: fused gate+up (gathered), then down + weighted scatter
    k_gateup<1><<<dim3(FE / 64, T_TOK / 128, NEXP), 128>>>(x, egw, euw, FE, HDIM);
    k_down<1><<<dim3(HDIM / 128, T_TOK / 128, NEXP), 128>>>(edw, out, HDIM, FE);

    // Shared expert path (reuses g_hdn)
    k_gateup<0><<<dim3(FS / 64, T_TOK / 128, 1), 128>>>(x, sgw, suw, FS, HDIM);
    k_down<0><<<dim3(HDIM / 128, T_TOK / 128, 1), 128>>>(sdw, out, HDIM, FS);
}

// round 14
// speedup vs baseline: 1.1649x; 1.0025x over previous
#include <cuda_runtime.h>
#include <cstdint>
#include <math.h>

#define T_TOK 4096
#define HDIM  2048
#define NEXP  16
#define TOPK  4
#define FE    1408
#define FS    5632

// Scratch: max(T*K*FE, T*FS) floats -- both exactly 23,068,672 (92.3 MB)
__device__ float g_hdn[23068672];
__device__ int   g_selE[T_TOK * TOPK];
__device__ float g_selW[T_TOK * TOPK];
__device__ int   g_rowtok[T_TOK * TOPK];
__device__ float g_roww[T_TOK * TOPK];
__device__ float g_sgate[T_TOK];
__device__ int   g_cnt[NEXP];
__device__ int   g_off[NEXP + 1];
__device__ int   g_cur[NEXP];

// ---------------------------------------------------------------------------
__global__ void k_init() {
    if (threadIdx.x < NEXP) g_cnt[threadIdx.x] = 0;
}

// ---------------------------------------------------------------------------
// Router: one warp per token (proven)
// ---------------------------------------------------------------------------
__global__ void k_router(const float* __restrict__ X,
                         const float* __restrict__ GW,
                         const float* __restrict__ SEGW) {
    int warp = (blockIdx.x * blockDim.x + threadIdx.x) >> 5;
    int lane = threadIdx.x & 31;
    if (warp >= T_TOK) return;
    const float* xr = X + (size_t)warp * HDIM;

    float part[NEXP];
    float ps = 0.f;
#pragma unroll
    for (int e = 0; e < NEXP; e++) part[e] = 0.f;

    for (int h = lane; h < HDIM; h += 32) {
        float xv = xr[h];
#pragma unroll
        for (int e = 0; e < NEXP; e++) part[e] += xv * GW[e * HDIM + h];
        ps += xv * SEGW[h];
    }
#pragma unroll
    for (int e = 0; e < NEXP; e++) {
#pragma unroll
        for (int o = 16; o > 0; o >>= 1)
            part[e] += __shfl_down_sync(0xffffffffu, part[e], o);
    }
#pragma unroll
    for (int o = 16; o > 0; o >>= 1)
        ps += __shfl_down_sync(0xffffffffu, ps, o);

    if (lane == 0) {
        float m = part[0];
#pragma unroll
        for (int e = 1; e < NEXP; e++) m = fmaxf(m, part[e]);
        float r[NEXP];
        float den = 0.f;
#pragma unroll
        for (int e = 0; e < NEXP; e++) { r[e] = expf(part[e] - m); den += r[e]; }
        float inv = 1.f / den;
#pragma unroll
        for (int e = 0; e < NEXP; e++) r[e] *= inv;

        int   se[TOPK];
        float sw[TOPK];
        float s4 = 0.f;
#pragma unroll
        for (int k = 0; k < TOPK; k++) {
            int bi = 0; float bv = -1.f;
#pragma unroll
            for (int e = 0; e < NEXP; e++)
                if (r[e] > bv) { bv = r[e]; bi = e; }
            se[k] = bi; sw[k] = bv; s4 += bv;
            r[bi] = -2.f;
        }
        float invs4 = 1.f / s4;
#pragma unroll
        for (int k = 0; k < TOPK; k++) {
            g_selE[warp * TOPK + k] = se[k];
            g_selW[warp * TOPK + k] = sw[k] * invs4;
            atomicAdd(&g_cnt[se[k]], 1);
        }
        g_sgate[warp] = 1.f / (1.f + expf(-ps));
    }
}

// ---------------------------------------------------------------------------
__global__ void k_offsets() {
    if (threadIdx.x == 0) {
        int acc = 0;
        for (int e = 0; e < NEXP; e++) {
            g_off[e] = acc;
            acc += g_cnt[e];
            g_cur[e] = 0;
        }
        g_off[NEXP] = acc;
    }
}

// ---------------------------------------------------------------------------
__global__ void k_assign() {
    int t = blockIdx.x * blockDim.x + threadIdx.x;
    if (t >= T_TOK) return;
#pragma unroll
    for (int k = 0; k < TOPK; k++) {
        int e = g_selE[t * TOPK + k];
        int slot = atomicAdd(&g_cur[e], 1);
        int pos = g_off[e] + slot;
        g_rowtok[pos] = t;
        g_roww[pos] = g_selW[t * TOPK + k];
    }
}

// ---------------------------------------------------------------------------
// Packed fp32x2 helpers (proven R11-R13)
// ---------------------------------------------------------------------------
__device__ __forceinline__ unsigned long long pk2(float x) {
    unsigned long long r;
    asm("mov.b64 %0, {%1, %1};" : "=l"(r) : "f"(x));
    return r;
}
__device__ __forceinline__ void fma2(unsigned long long& d,
                                     unsigned long long a,
                                     unsigned long long b) {
    asm("fma.rn.f32x2 %0, %1, %2, %0;" : "+l"(d) : "l"(a), "l"(b));
}
__device__ __forceinline__ float2 up2(unsigned long long v) {
    float lo, hi;
    asm("mov.b64 {%0, %1}, %2;" : "=f"(lo), "=f"(hi) : "l"(v));
    return make_float2(lo, hi);
}

// ---------------------------------------------------------------------------
// Fused gate+up GEMM, 128(M) x 64-logical(N) (gate+up combined = 128 B rows),
// BK=16, 128 threads (8 ty x 16 tx), per-thread 16 rows x (4g+4u) cols.
// Register-staged double buffering, one barrier/iter, FFMA2. (proven R13)
// ---------------------------------------------------------------------------
template <int GATHER>
__global__ void __launch_bounds__(128, 2)
k_gateup(const float* __restrict__ X,
         const float* __restrict__ Wgb,
         const float* __restrict__ Wub,
         int N, int Kd) {
    int rows, base;
    const float* Wg;
    const float* Wu;
    if (GATHER) {
        int e = blockIdx.z;
        rows = g_cnt[e];
        base = g_off[e];
        size_t wo = (size_t)e * N * Kd;
        Wg = Wgb + wo; Wu = Wub + wo;
    } else {
        rows = T_TOK; base = 0; Wg = Wgb; Wu = Wub;
    }
    int rowBase = blockIdx.y * 128;
    if (rowBase >= rows) return;
    int colBase = blockIdx.x * 64;   // 64 logical cols (each gate+up)

    __shared__ float As[2][16][132];
    __shared__ float Bs[2][16][132];   // rows 0-63: Wg cols, 64-127: Wu cols

    const int tid = threadIdx.x;
    const int tx = tid & 15;   // 4 logical cols
    const int ty = tid >> 4;   // 16 rows (8 pairs)

    int ar[4], ac[4];
    const float* aptr[4];
    bool aval[4];
    const float* bptr[4];
    int br[4], bc[4];
#pragma unroll
    for (int i = 0; i < 4; i++) {
        int idx = tid + i * 128;
        ar[i] = idx >> 2;
        ac[i] = (idx & 3) * 4;
        int grow = rowBase + ar[i];
        aval[i] = grow < rows;
        if (GATHER) {
            int tok = aval[i] ? g_rowtok[base + grow] : 0;
            aptr[i] = X + (size_t)tok * Kd + ac[i];
        } else {
            aptr[i] = X + (size_t)(aval[i] ? grow : 0) * Kd + ac[i];
        }
        br[i] = idx >> 2;
        bc[i] = (idx & 3) * 4;
        if (br[i] < 64)
            bptr[i] = Wg + (size_t)(colBase + br[i]) * Kd + bc[i];
        else
            bptr[i] = Wu + (size_t)(colBase + br[i] - 64) * Kd + bc[i];
    }

    unsigned long long accg2[8][4];
    unsigned long long accu2[8][4];
#pragma unroll
    for (int p = 0; p < 8; p++)
#pragma unroll
        for (int j = 0; j < 4; j++) { accg2[p][j] = 0ULL; accu2[p][j] = 0ULL; }

    const int KT = Kd >> 4;

    float4 sva[4], svb[4];
#pragma unroll
    for (int i = 0; i < 4; i++) {
        sva[i] = aval[i] ? *reinterpret_cast<const float4*>(aptr[i])
                         : make_float4(0.f, 0.f, 0.f, 0.f);
        svb[i] = *reinterpret_cast<const float4*>(bptr[i]);
    }
#pragma unroll
    for (int i = 0; i < 4; i++) {
        As[0][ac[i] + 0][ar[i]] = sva[i].x;
        As[0][ac[i] + 1][ar[i]] = sva[i].y;
        As[0][ac[i] + 2][ar[i]] = sva[i].z;
        As[0][ac[i] + 3][ar[i]] = sva[i].w;
        Bs[0][bc[i] + 0][br[i]] = svb[i].x;
        Bs[0][bc[i] + 1][br[i]] = svb[i].y;
        Bs[0][bc[i] + 2][br[i]] = svb[i].z;
        Bs[0][bc[i] + 3][br[i]] = svb[i].w;
    }
    __syncthreads();

    for (int kt = 0; kt < KT; kt++) {
        int cur = kt & 1;
        if (kt + 1 < KT) {
            int k0 = (kt + 1) << 4;
#pragma unroll
            for (int i = 0; i < 4; i++) {
                sva[i] = aval[i] ? *reinterpret_cast<const float4*>(aptr[i] + k0)
                                 : make_float4(0.f, 0.f, 0.f, 0.f);
                svb[i] = *reinterpret_cast<const float4*>(bptr[i] + k0);
            }
        }
#pragma unroll
        for (int kk = 0; kk < 16; kk++) {
            const ulonglong2* ap =
                reinterpret_cast<const ulonglong2*>(&As[cur][kk][ty * 16]);
            ulonglong2 av0 = ap[0], av1 = ap[1], av2 = ap[2], av3 = ap[3];
            unsigned long long a2[8] = {av0.x, av0.y, av1.x, av1.y,
                                        av2.x, av2.y, av3.x, av3.y};
            float4 bg = *reinterpret_cast<const float4*>(&Bs[cur][kk][tx * 4]);
            float4 bu = *reinterpret_cast<const float4*>(&Bs[cur][kk][64 + tx * 4]);
            unsigned long long bg2[4] = {pk2(bg.x), pk2(bg.y), pk2(bg.z), pk2(bg.w)};
            unsigned long long bu2[4] = {pk2(bu.x), pk2(bu.y), pk2(bu.z), pk2(bu.w)};
#pragma unroll
            for (int p = 0; p < 8; p++) {
#pragma unroll
                for (int j = 0; j < 4; j++) {
                    fma2(accg2[p][j], a2[p], bg2[j]);
                    fma2(accu2[p][j], a2[p], bu2[j]);
                }
            }
        }
        if (kt + 1 < KT) {
            int nxt = cur ^ 1;
#pragma unroll
            for (int i = 0; i < 4; i++) {
                As[nxt][ac[i] + 0][ar[i]] = sva[i].x;
                As[nxt][ac[i] + 1][ar[i]] = sva[i].y;
                As[nxt][ac[i] + 2][ar[i]] = sva[i].z;
                As[nxt][ac[i] + 3][ar[i]] = sva[i].w;
                Bs[nxt][bc[i] + 0][br[i]] = svb[i].x;
                Bs[nxt][bc[i] + 1][br[i]] = svb[i].y;
                Bs[nxt][bc[i] + 2][br[i]] = svb[i].z;
                Bs[nxt][bc[i] + 3][br[i]] = svb[i].w;
            }
        }
        __syncthreads();
    }

    // epilogue: silu(g)*u -> g_hdn (pair p covers rows ty*16+2p, +1)
#pragma unroll
    for (int p = 0; p < 8; p++) {
        float2 g2[4], u2[4];
#pragma unroll
        for (int j = 0; j < 4; j++) { g2[j] = up2(accg2[p][j]); u2[j] = up2(accu2[p][j]); }
        int growL = rowBase + ty * 16 + 2 * p;
        if (growL < rows) {
            float4 hv;
            hv.x = (g2[0].x / (1.f + expf(-g2[0].x))) * u2[0].x;
            hv.y = (g2[1].x / (1.f + expf(-g2[1].x))) * u2[1].x;
            hv.z = (g2[2].x / (1.f + expf(-g2[2].x))) * u2[2].x;
            hv.w = (g2[3].x / (1.f + expf(-g2[3].x))) * u2[3].x;
            *reinterpret_cast<float4*>(
                &g_hdn[(size_t)(base + growL) * N + colBase + tx * 4]) = hv;
        }
        int growH = growL + 1;
        if (growH < rows) {
            float4 hv;
            hv.x = (g2[0].y / (1.f + expf(-g2[0].y))) * u2[0].y;
            hv.y = (g2[1].y / (1.f + expf(-g2[1].y))) * u2[1].y;
            hv.z = (g2[2].y / (1.f + expf(-g2[2].y))) * u2[2].y;
            hv.w = (g2[3].y / (1.f + expf(-g2[3].y))) * u2[3].y;
            *reinterpret_cast<float4*>(
                &g_hdn[(size_t)(base + growH) * N + colBase + tx * 4]) = hv;
        }
    }
}

// ---------------------------------------------------------------------------
// Down GEMM, 128(M) x 128(N), BK=16, 128 threads, per-thread 16 rows x 8 cols,
// double-buffered, FFMA2.
// GATHER=1: expert path, weighted atomicAdd scatter (on top of shared init).
// GATHER=0: shared path, sigmoid-weighted PLAIN STORES (initializes out,
//           replaces the memset; every (token,col) written exactly once).
// ---------------------------------------------------------------------------
template <int GATHER>
__global__ void __launch_bounds__(128, 2)
k_down(const float* __restrict__ Wdb,
       float* __restrict__ Out,
       int N, int Kd) {
    int rows, base;
    const float* Wd;
    if (GATHER) {
        int e = blockIdx.z;
        rows = g_cnt[e];
        base = g_off[e];
        Wd = Wdb + (size_t)e * N * Kd;
    } else {
        rows = T_TOK; base = 0; Wd = Wdb;
    }
    int rowBase = blockIdx.y * 128;
    if (rowBase >= rows) return;
    int colBase = blockIdx.x * 128;

    __shared__ float As[2][16][132];
    __shared__ float Bs[2][16][132];

    const int tid = threadIdx.x;
    const int tx = tid & 15;
    const int ty = tid >> 4;

    int ar[4], ac[4];
    const float* aptr[4];
    bool aval[4];
    const float* bptr[4];
    int br[4], bc[4];
#pragma unroll
    for (int i = 0; i < 4; i++) {
        int idx = tid + i * 128;
        ar[i] = idx >> 2;
        ac[i] = (idx & 3) * 4;
        int grow = rowBase + ar[i];
        aval[i] = grow < rows;
        aptr[i] = g_hdn + (size_t)(base + (aval[i] ? grow : 0)) * Kd + ac[i];
        br[i] = idx >> 2;
        bc[i] = (idx & 3) * 4;
        bptr[i] = Wd + (size_t)(colBase + br[i]) * Kd + bc[i];
    }

    unsigned long long acc2[8][8];
#pragma unroll
    for (int p = 0; p < 8; p++)
#pragma unroll
        for (int j = 0; j < 8; j++) acc2[p][j] = 0ULL;

    const int KT = Kd >> 4;

    float4 sva[4], svb[4];
#pragma unroll
    for (int i = 0; i < 4; i++) {
        sva[i] = aval[i] ? *reinterpret_cast<const float4*>(aptr[i])
                         : make_float4(0.f, 0.f, 0.f, 0.f);
        svb[i] = *reinterpret_cast<const float4*>(bptr[i]);
    }
#pragma unroll
    for (int i = 0; i < 4; i++) {
        As[0][ac[i] + 0][ar[i]] = sva[i].x;
        As[0][ac[i] + 1][ar[i]] = sva[i].y;
        As[0][ac[i] + 2][ar[i]] = sva[i].z;
        As[0][ac[i] + 3][ar[i]] = sva[i].w;
        Bs[0][bc[i] + 0][br[i]] = svb[i].x;
        Bs[0][bc[i] + 1][br[i]] = svb[i].y;
        Bs[0][bc[i] + 2][br[i]] = svb[i].z;
        Bs[0][bc[i] + 3][br[i]] = svb[i].w;
    }
    __syncthreads();

    for (int kt = 0; kt < KT; kt++) {
        int cur = kt & 1;
        if (kt + 1 < KT) {
            int k0 = (kt + 1) << 4;
#pragma unroll
            for (int i = 0; i < 4; i++) {
                sva[i] = aval[i] ? *reinterpret_cast<const float4*>(aptr[i] + k0)
                                 : make_float4(0.f, 0.f, 0.f, 0.f);
                svb[i] = *reinterpret_cast<const float4*>(bptr[i] + k0);
            }
        }
#pragma unroll
        for (int kk = 0; kk < 16; kk++) {
            const ulonglong2* ap =
                reinterpret_cast<const ulonglong2*>(&As[cur][kk][ty * 16]);
            ulonglong2 av0 = ap[0], av1 = ap[1], av2 = ap[2], av3 = ap[3];
            unsigned long long a2[8] = {av0.x, av0.y, av1.x, av1.y,
                                        av2.x, av2.y, av3.x, av3.y};
            float4 b0 = *reinterpret_cast<const float4*>(&Bs[cur][kk][tx * 4]);
            float4 b1 = *reinterpret_cast<const float4*>(&Bs[cur][kk][64 + tx * 4]);
            unsigned long long b2[8] = {pk2(b0.x), pk2(b0.y), pk2(b0.z), pk2(b0.w),
                                        pk2(b1.x), pk2(b1.y), pk2(b1.z), pk2(b1.w)};
#pragma unroll
            for (int p = 0; p < 8; p++)
#pragma unroll
                for (int j = 0; j < 8; j++)
                    fma2(acc2[p][j], a2[p], b2[j]);
        }
        if (kt + 1 < KT) {
            int nxt = cur ^ 1;
#pragma unroll
            for (int i = 0; i < 4; i++) {
                As[nxt][ac[i] + 0][ar[i]] = sva[i].x;
                As[nxt][ac[i] + 1][ar[i]] = sva[i].y;
                As[nxt][ac[i] + 2][ar[i]] = sva[i].z;
                As[nxt][ac[i] + 3][ar[i]] = sva[i].w;
                Bs[nxt][bc[i] + 0][br[i]] = svb[i].x;
                Bs[nxt][bc[i] + 1][br[i]] = svb[i].y;
                Bs[nxt][bc[i] + 2][br[i]] = svb[i].z;
                Bs[nxt][bc[i] + 3][br[i]] = svb[i].w;
            }
        }
        __syncthreads();
    }

    // epilogue
#pragma unroll
    for (int p = 0; p < 8; p++) {
        float2 c2[8];
#pragma unroll
        for (int j = 0; j < 8; j++) c2[j] = up2(acc2[p][j]);
#pragma unroll
        for (int half = 0; half < 2; half++) {
            int grow = rowBase + ty * 16 + 2 * p + half;
            if (grow >= rows) continue;
            if (GATHER) {
                int tok = g_rowtok[base + grow];
                float w = g_roww[base + grow];
                float* op0 = Out + (size_t)tok * N + colBase + tx * 4;
                float* op1 = op0 + 64;
#pragma unroll
                for (int j = 0; j < 4; j++) {
                    float v0 = half ? c2[j].y : c2[j].x;
                    float v1 = half ? c2[j + 4].y : c2[j + 4].x;
                    atomicAdd(op0 + j, w * v0);
                    atomicAdd(op1 + j, w * v1);
                }
            } else {
                float w = g_sgate[grow];
                float* op0 = Out + (size_t)grow * N + colBase + tx * 4;
                float4 s0, s1;
                s0.x = w * (half ? c2[0].y : c2[0].x);
                s0.y = w * (half ? c2[1].y : c2[1].x);
                s0.z = w * (half ? c2[2].y : c2[2].x);
                s0.w = w * (half ? c2[3].y : c2[3].x);
                s1.x = w * (half ? c2[4].y : c2[4].x);
                s1.y = w * (half ? c2[5].y : c2[5].x);
                s1.z = w * (half ? c2[6].y : c2[6].x);
                s1.w = w * (half ? c2[7].y : c2[7].x);
                *reinterpret_cast<float4*>(op0) = s0;
                *reinterpret_cast<float4*>(op0 + 64) = s1;
            }
        }
    }
}

// ---------------------------------------------------------------------------
extern "C" void kernel_launch(void* const* d_in, const int* in_sizes, int n_in,
                              void* d_out, int out_size) {
    const float* x    = (const float*)d_in[0];  // [B,S,H]
    const float* gw   = (const float*)d_in[1];  // [E,H]
    const float* egw  = (const float*)d_in[2];  // [E,FE,H]
    const float* euw  = (const float*)d_in[3];  // [E,FE,H]
    const float* edw  = (const float*)d_in[4];  // [E,H,FE]
    const float* sgw  = (const float*)d_in[5];  // [FS,H]
    const float* suw  = (const float*)d_in[6];  // [FS,H]
    const float* sdw  = (const float*)d_in[7];  // [H,FS]
    const float* segw = (const float*)d_in[8];  // [1,H]
    float* out = (float*)d_out;

    k_init<<<1, 32>>>();
    k_router<<<T_TOK / 8, 256>>>(x, gw, segw);
    k_offsets<<<1, 32>>>();
    k_assign<<<T_TOK / 256, 256>>>();

    // Shared path FIRST (5th launch = k_gateup<0> -> ncu profiles the GEMM).
    // Shared down does plain weighted stores, initializing out (no memset).
    k_gateup<0><<<dim3(FS / 64, T_TOK / 128, 1), 128>>>(x, sgw, suw, FS, HDIM);
    k_down<0><<<dim3(HDIM / 128, T_TOK / 128, 1), 128>>>(sdw, out, HDIM, FS);

    // Expert path: fused gate+up (gathered), then down + weighted atomic add
    k_gateup<1><<<dim3(FE / 64, T_TOK / 128, NEXP), 128>>>(x, egw, euw, FE, HDIM);
    k_down<1><<<dim3(HDIM / 128, T_TOK / 128, NEXP), 128>>>(edw, out, HDIM, FE);
}

// round 15
// speedup vs baseline: 1.1675x; 1.0022x over previous
#include <cuda_runtime.h>
#include <cstdint>
#include <math.h>

#define T_TOK 4096
#define HDIM  2048
#define NEXP  16
#define TOPK  4
#define FE    1408
#define FS    5632

// Scratch: max(T*K*FE, T*FS) floats -- both exactly 23,068,672 (92.3 MB)
__device__ float g_hdn[23068672];
__device__ int   g_selE[T_TOK * TOPK];
__device__ float g_selW[T_TOK * TOPK];
__device__ int   g_rowtok[T_TOK * TOPK];
__device__ float g_roww[T_TOK * TOPK];
__device__ float g_sgate[T_TOK];
__device__ int   g_cnt[NEXP];
__device__ int   g_off[NEXP + 1];
__device__ int   g_cur[NEXP];

// ---------------------------------------------------------------------------
// Router: one warp per token (proven; global atomic counting removed)
// ---------------------------------------------------------------------------
__global__ void k_router(const float* __restrict__ X,
                         const float* __restrict__ GW,
                         const float* __restrict__ SEGW) {
    int warp = (blockIdx.x * blockDim.x + threadIdx.x) >> 5;
    int lane = threadIdx.x & 31;
    if (warp >= T_TOK) return;
    const float* xr = X + (size_t)warp * HDIM;

    float part[NEXP];
    float ps = 0.f;
#pragma unroll
    for (int e = 0; e < NEXP; e++) part[e] = 0.f;

    for (int h = lane; h < HDIM; h += 32) {
        float xv = xr[h];
#pragma unroll
        for (int e = 0; e < NEXP; e++) part[e] += xv * GW[e * HDIM + h];
        ps += xv * SEGW[h];
    }
#pragma unroll
    for (int e = 0; e < NEXP; e++) {
#pragma unroll
        for (int o = 16; o > 0; o >>= 1)
            part[e] += __shfl_down_sync(0xffffffffu, part[e], o);
    }
#pragma unroll
    for (int o = 16; o > 0; o >>= 1)
        ps += __shfl_down_sync(0xffffffffu, ps, o);

    if (lane == 0) {
        float m = part[0];
#pragma unroll
        for (int e = 1; e < NEXP; e++) m = fmaxf(m, part[e]);
        float r[NEXP];
        float den = 0.f;
#pragma unroll
        for (int e = 0; e < NEXP; e++) { r[e] = expf(part[e] - m); den += r[e]; }
        float inv = 1.f / den;
#pragma unroll
        for (int e = 0; e < NEXP; e++) r[e] *= inv;

        int   se[TOPK];
        float sw[TOPK];
        float s4 = 0.f;
#pragma unroll
        for (int k = 0; k < TOPK; k++) {
            int bi = 0; float bv = -1.f;
#pragma unroll
            for (int e = 0; e < NEXP; e++)
                if (r[e] > bv) { bv = r[e]; bi = e; }
            se[k] = bi; sw[k] = bv; s4 += bv;
            r[bi] = -2.f;
        }
        float invs4 = 1.f / s4;
#pragma unroll
        for (int k = 0; k < TOPK; k++) {
            g_selE[warp * TOPK + k] = se[k];
            g_selW[warp * TOPK + k] = sw[k] * invs4;
        }
        g_sgate[warp] = 1.f / (1.f + expf(-ps));
    }
}

// ---------------------------------------------------------------------------
// offsets: single block; histogram selE in smem, prefix-sum, reset cursors.
// Replaces k_init + router-side atomics.
// ---------------------------------------------------------------------------
__global__ void k_offsets() {
    __shared__ int scnt[NEXP];
    int tid = threadIdx.x;
    if (tid < NEXP) scnt[tid] = 0;
    __syncthreads();
    for (int i = tid; i < T_TOK * TOPK; i += blockDim.x)
        atomicAdd(&scnt[g_selE[i]], 1);
    __syncthreads();
    if (tid == 0) {
        int acc = 0;
        for (int e = 0; e < NEXP; e++) {
            g_cnt[e] = scnt[e];
            g_off[e] = acc;
            acc += scnt[e];
            g_cur[e] = 0;
        }
        g_off[NEXP] = acc;
    }
}

// ---------------------------------------------------------------------------
__global__ void k_assign() {
    int t = blockIdx.x * blockDim.x + threadIdx.x;
    if (t >= T_TOK) return;
#pragma unroll
    for (int k = 0; k < TOPK; k++) {
        int e = g_selE[t * TOPK + k];
        int slot = atomicAdd(&g_cur[e], 1);
        int pos = g_off[e] + slot;
        g_rowtok[pos] = t;
        g_roww[pos] = g_selW[t * TOPK + k];
    }
}

// ---------------------------------------------------------------------------
// Packed fp32x2 helpers (proven R11-R14)
// ---------------------------------------------------------------------------
__device__ __forceinline__ unsigned long long pk2(float x) {
    unsigned long long r;
    asm("mov.b64 %0, {%1, %1};" : "=l"(r) : "f"(x));
    return r;
}
__device__ __forceinline__ void fma2(unsigned long long& d,
                                     unsigned long long a,
                                     unsigned long long b) {
    asm("fma.rn.f32x2 %0, %1, %2, %0;" : "+l"(d) : "l"(a), "l"(b));
}
__device__ __forceinline__ float2 up2(unsigned long long v) {
    float lo, hi;
    asm("mov.b64 {%0, %1}, %2;" : "=f"(lo), "=f"(hi) : "l"(v));
    return make_float2(lo, hi);
}

// ---------------------------------------------------------------------------
// Fused gate+up GEMM (byte-identical core to R14, proven at 10.24ms)
// ---------------------------------------------------------------------------
template <int GATHER>
__global__ void __launch_bounds__(128, 2)
k_gateup(const float* __restrict__ X,
         const float* __restrict__ Wgb,
         const float* __restrict__ Wub,
         int N, int Kd) {
    int rows, base;
    const float* Wg;
    const float* Wu;
    if (GATHER) {
        int e = blockIdx.z;
        rows = g_cnt[e];
        base = g_off[e];
        size_t wo = (size_t)e * N * Kd;
        Wg = Wgb + wo; Wu = Wub + wo;
    } else {
        rows = T_TOK; base = 0; Wg = Wgb; Wu = Wub;
    }
    int rowBase = blockIdx.y * 128;
    if (rowBase >= rows) return;
    int colBase = blockIdx.x * 64;

    __shared__ float As[2][16][132];
    __shared__ float Bs[2][16][132];

    const int tid = threadIdx.x;
    const int tx = tid & 15;
    const int ty = tid >> 4;

    int ar[4], ac[4];
    const float* aptr[4];
    bool aval[4];
    const float* bptr[4];
    int br[4], bc[4];
#pragma unroll
    for (int i = 0; i < 4; i++) {
        int idx = tid + i * 128;
        ar[i] = idx >> 2;
        ac[i] = (idx & 3) * 4;
        int grow = rowBase + ar[i];
        aval[i] = grow < rows;
        if (GATHER) {
            int tok = aval[i] ? g_rowtok[base + grow] : 0;
            aptr[i] = X + (size_t)tok * Kd + ac[i];
        } else {
            aptr[i] = X + (size_t)(aval[i] ? grow : 0) * Kd + ac[i];
        }
        br[i] = idx >> 2;
        bc[i] = (idx & 3) * 4;
        if (br[i] < 64)
            bptr[i] = Wg + (size_t)(colBase + br[i]) * Kd + bc[i];
        else
            bptr[i] = Wu + (size_t)(colBase + br[i] - 64) * Kd + bc[i];
    }

    unsigned long long accg2[8][4];
    unsigned long long accu2[8][4];
#pragma unroll
    for (int p = 0; p < 8; p++)
#pragma unroll
        for (int j = 0; j < 4; j++) { accg2[p][j] = 0ULL; accu2[p][j] = 0ULL; }

    const int KT = Kd >> 4;

    float4 sva[4], svb[4];
#pragma unroll
    for (int i = 0; i < 4; i++) {
        sva[i] = aval[i] ? *reinterpret_cast<const float4*>(aptr[i])
                         : make_float4(0.f, 0.f, 0.f, 0.f);
        svb[i] = *reinterpret_cast<const float4*>(bptr[i]);
    }
#pragma unroll
    for (int i = 0; i < 4; i++) {
        As[0][ac[i] + 0][ar[i]] = sva[i].x;
        As[0][ac[i] + 1][ar[i]] = sva[i].y;
        As[0][ac[i] + 2][ar[i]] = sva[i].z;
        As[0][ac[i] + 3][ar[i]] = sva[i].w;
        Bs[0][bc[i] + 0][br[i]] = svb[i].x;
        Bs[0][bc[i] + 1][br[i]] = svb[i].y;
        Bs[0][bc[i] + 2][br[i]] = svb[i].z;
        Bs[0][bc[i] + 3][br[i]] = svb[i].w;
    }
    __syncthreads();

    for (int kt = 0; kt < KT; kt++) {
        int cur = kt & 1;
        if (kt + 1 < KT) {
            int k0 = (kt + 1) << 4;
#pragma unroll
            for (int i = 0; i < 4; i++) {
                sva[i] = aval[i] ? *reinterpret_cast<const float4*>(aptr[i] + k0)
                                 : make_float4(0.f, 0.f, 0.f, 0.f);
                svb[i] = *reinterpret_cast<const float4*>(bptr[i] + k0);
            }
        }
#pragma unroll
        for (int kk = 0; kk < 16; kk++) {
            const ulonglong2* ap =
                reinterpret_cast<const ulonglong2*>(&As[cur][kk][ty * 16]);
            ulonglong2 av0 = ap[0], av1 = ap[1], av2 = ap[2], av3 = ap[3];
            unsigned long long a2[8] = {av0.x, av0.y, av1.x, av1.y,
                                        av2.x, av2.y, av3.x, av3.y};
            float4 bg = *reinterpret_cast<const float4*>(&Bs[cur][kk][tx * 4]);
            float4 bu = *reinterpret_cast<const float4*>(&Bs[cur][kk][64 + tx * 4]);
            unsigned long long bg2[4] = {pk2(bg.x), pk2(bg.y), pk2(bg.z), pk2(bg.w)};
            unsigned long long bu2[4] = {pk2(bu.x), pk2(bu.y), pk2(bu.z), pk2(bu.w)};
#pragma unroll
            for (int p = 0; p < 8; p++) {
#pragma unroll
                for (int j = 0; j < 4; j++) {
                    fma2(accg2[p][j], a2[p], bg2[j]);
                    fma2(accu2[p][j], a2[p], bu2[j]);
                }
            }
        }
        if (kt + 1 < KT) {
            int nxt = cur ^ 1;
#pragma unroll
            for (int i = 0; i < 4; i++) {
                As[nxt][ac[i] + 0][ar[i]] = sva[i].x;
                As[nxt][ac[i] + 1][ar[i]] = sva[i].y;
                As[nxt][ac[i] + 2][ar[i]] = sva[i].z;
                As[nxt][ac[i] + 3][ar[i]] = sva[i].w;
                Bs[nxt][bc[i] + 0][br[i]] = svb[i].x;
                Bs[nxt][bc[i] + 1][br[i]] = svb[i].y;
                Bs[nxt][bc[i] + 2][br[i]] = svb[i].z;
                Bs[nxt][bc[i] + 3][br[i]] = svb[i].w;
            }
        }
        __syncthreads();
    }

#pragma unroll
    for (int p = 0; p < 8; p++) {
        float2 g2[4], u2[4];
#pragma unroll
        for (int j = 0; j < 4; j++) { g2[j] = up2(accg2[p][j]); u2[j] = up2(accu2[p][j]); }
        int growL = rowBase + ty * 16 + 2 * p;
        if (growL < rows) {
            float4 hv;
            hv.x = (g2[0].x / (1.f + expf(-g2[0].x))) * u2[0].x;
            hv.y = (g2[1].x / (1.f + expf(-g2[1].x))) * u2[1].x;
            hv.z = (g2[2].x / (1.f + expf(-g2[2].x))) * u2[2].x;
            hv.w = (g2[3].x / (1.f + expf(-g2[3].x))) * u2[3].x;
            *reinterpret_cast<float4*>(
                &g_hdn[(size_t)(base + growL) * N + colBase + tx * 4]) = hv;
        }
        int growH = growL + 1;
        if (growH < rows) {
            float4 hv;
            hv.x = (g2[0].y / (1.f + expf(-g2[0].y))) * u2[0].y;
            hv.y = (g2[1].y / (1.f + expf(-g2[1].y))) * u2[1].y;
            hv.z = (g2[2].y / (1.f + expf(-g2[2].y))) * u2[2].y;
            hv.w = (g2[3].y / (1.f + expf(-g2[3].y))) * u2[3].y;
            *reinterpret_cast<float4*>(
                &g_hdn[(size_t)(base + growH) * N + colBase + tx * 4]) = hv;
        }
    }
}

// ---------------------------------------------------------------------------
// Down GEMM (byte-identical core to R14)
// ---------------------------------------------------------------------------
template <int GATHER>
__global__ void __launch_bounds__(128, 2)
k_down(const float* __restrict__ Wdb,
       float* __restrict__ Out,
       int N, int Kd) {
    int rows, base;
    const float* Wd;
    if (GATHER) {
        int e = blockIdx.z;
        rows = g_cnt[e];
        base = g_off[e];
        Wd = Wdb + (size_t)e * N * Kd;
    } else {
        rows = T_TOK; base = 0; Wd = Wdb;
    }
    int rowBase = blockIdx.y * 128;
    if (rowBase >= rows) return;
    int colBase = blockIdx.x * 128;

    __shared__ float As[2][16][132];
    __shared__ float Bs[2][16][132];

    const int tid = threadIdx.x;
    const int tx = tid & 15;
    const int ty = tid >> 4;

    int ar[4], ac[4];
    const float* aptr[4];
    bool aval[4];
    const float* bptr[4];
    int br[4], bc[4];
#pragma unroll
    for (int i = 0; i < 4; i++) {
        int idx = tid + i * 128;
        ar[i] = idx >> 2;
        ac[i] = (idx & 3) * 4;
        int grow = rowBase + ar[i];
        aval[i] = grow < rows;
        aptr[i] = g_hdn + (size_t)(base + (aval[i] ? grow : 0)) * Kd + ac[i];
        br[i] = idx >> 2;
        bc[i] = (idx & 3) * 4;
        bptr[i] = Wd + (size_t)(colBase + br[i]) * Kd + bc[i];
    }

    unsigned long long acc2[8][8];
#pragma unroll
    for (int p = 0; p < 8; p++)
#pragma unroll
        for (int j = 0; j < 8; j++) acc2[p][j] = 0ULL;

    const int KT = Kd >> 4;

    float4 sva[4], svb[4];
#pragma unroll
    for (int i = 0; i < 4; i++) {
        sva[i] = aval[i] ? *reinterpret_cast<const float4*>(aptr[i])
                         : make_float4(0.f, 0.f, 0.f, 0.f);
        svb[i] = *reinterpret_cast<const float4*>(bptr[i]);
    }
#pragma unroll
    for (int i = 0; i < 4; i++) {
        As[0][ac[i] + 0][ar[i]] = sva[i].x;
        As[0][ac[i] + 1][ar[i]] = sva[i].y;
        As[0][ac[i] + 2][ar[i]] = sva[i].z;
        As[0][ac[i] + 3][ar[i]] = sva[i].w;
        Bs[0][bc[i] + 0][br[i]] = svb[i].x;
        Bs[0][bc[i] + 1][br[i]] = svb[i].y;
        Bs[0][bc[i] + 2][br[i]] = svb[i].z;
        Bs[0][bc[i] + 3][br[i]] = svb[i].w;
    }
    __syncthreads();

    for (int kt = 0; kt < KT; kt++) {
        int cur = kt & 1;
        if (kt + 1 < KT) {
            int k0 = (kt + 1) << 4;
#pragma unroll
            for (int i = 0; i < 4; i++) {
                sva[i] = aval[i] ? *reinterpret_cast<const float4*>(aptr[i] + k0)
                                 : make_float4(0.f, 0.f, 0.f, 0.f);
                svb[i] = *reinterpret_cast<const float4*>(bptr[i] + k0);
            }
        }
#pragma unroll
        for (int kk = 0; kk < 16; kk++) {
            const ulonglong2* ap =
                reinterpret_cast<const ulonglong2*>(&As[cur][kk][ty * 16]);
            ulonglong2 av0 = ap[0], av1 = ap[1], av2 = ap[2], av3 = ap[3];
            unsigned long long a2[8] = {av0.x, av0.y, av1.x, av1.y,
                                        av2.x, av2.y, av3.x, av3.y};
            float4 b0 = *reinterpret_cast<const float4*>(&Bs[cur][kk][tx * 4]);
            float4 b1 = *reinterpret_cast<const float4*>(&Bs[cur][kk][64 + tx * 4]);
            unsigned long long b2[8] = {pk2(b0.x), pk2(b0.y), pk2(b0.z), pk2(b0.w),
                                        pk2(b1.x), pk2(b1.y), pk2(b1.z), pk2(b1.w)};
#pragma unroll
            for (int p = 0; p < 8; p++)
#pragma unroll
                for (int j = 0; j < 8; j++)
                    fma2(acc2[p][j], a2[p], b2[j]);
        }
        if (kt + 1 < KT) {
            int nxt = cur ^ 1;
#pragma unroll
            for (int i = 0; i < 4; i++) {
                As[nxt][ac[i] + 0][ar[i]] = sva[i].x;
                As[nxt][ac[i] + 1][ar[i]] = sva[i].y;
                As[nxt][ac[i] + 2][ar[i]] = sva[i].z;
                As[nxt][ac[i] + 3][ar[i]] = sva[i].w;
                Bs[nxt][bc[i] + 0][br[i]] = svb[i].x;
                Bs[nxt][bc[i] + 1][br[i]] = svb[i].y;
                Bs[nxt][bc[i] + 2][br[i]] = svb[i].z;
                Bs[nxt][bc[i] + 3][br[i]] = svb[i].w;
            }
        }
        __syncthreads();
    }

#pragma unroll
    for (int p = 0; p < 8; p++) {
        float2 c2[8];
#pragma unroll
        for (int j = 0; j < 8; j++) c2[j] = up2(acc2[p][j]);
#pragma unroll
        for (int half = 0; half < 2; half++) {
            int grow = rowBase + ty * 16 + 2 * p + half;
            if (grow >= rows) continue;
            if (GATHER) {
                int tok = g_rowtok[base + grow];
                float w = g_roww[base + grow];
                float* op0 = Out + (size_t)tok * N + colBase + tx * 4;
                float* op1 = op0 + 64;
#pragma unroll
                for (int j = 0; j < 4; j++) {
                    float v0 = half ? c2[j].y : c2[j].x;
                    float v1 = half ? c2[j + 4].y : c2[j + 4].x;
                    atomicAdd(op0 + j, w * v0);
                    atomicAdd(op1 + j, w * v1);
                }
            } else {
                float w = g_sgate[grow];
                float* op0 = Out + (size_t)grow * N + colBase + tx * 4;
                float4 s0, s1;
                s0.x = w * (half ? c2[0].y : c2[0].x);
                s0.y = w * (half ? c2[1].y : c2[1].x);
                s0.z = w * (half ? c2[2].y : c2[2].x);
                s0.w = w * (half ? c2[3].y : c2[3].x);
                s1.x = w * (half ? c2[4].y : c2[4].x);
                s1.y = w * (half ? c2[5].y : c2[5].x);
                s1.z = w * (half ? c2[6].y : c2[6].x);
                s1.w = w * (half ? c2[7].y : c2[7].x);
                *reinterpret_cast<float4*>(op0) = s0;
                *reinterpret_cast<float4*>(op0 + 64) = s1;
            }
        }
    }
}

// ---------------------------------------------------------------------------
extern "C" void kernel_launch(void* const* d_in, const int* in_sizes, int n_in,
                              void* d_out, int out_size) {
    const float* x    = (const float*)d_in[0];  // [B,S,H]
    const float* gw   = (const float*)d_in[1];  // [E,H]
    const float* egw  = (const float*)d_in[2];  // [E,FE,H]
    const float* euw  = (const float*)d_in[3];  // [E,FE,H]
    const float* edw  = (const float*)d_in[4];  // [E,H,FE]
    const float* sgw  = (const float*)d_in[5];  // [FS,H]
    const float* suw  = (const float*)d_in[6];  // [FS,H]
    const float* sdw  = (const float*)d_in[7];  // [H,FS]
    const float* segw = (const float*)d_in[8];  // [1,H]
    float* out = (float*)d_out;

    k_router<<<T_TOK / 8, 256>>>(x, gw, segw);       // 1
    k_offsets<<<1, 256>>>();                          // 2 (histogram+prefix)
    k_assign<<<T_TOK / 256, 256>>>();                 // 3

    // 4th launch = GEMM (profiled slot). Shared path first; its down kernel
    // initializes out with plain weighted stores (no memset needed).
    k_gateup<0><<<dim3(FS / 64, T_TOK / 128, 1), 128>>>(x, sgw, suw, FS, HDIM);
    k_down<0><<<dim3(HDIM / 128, T_TOK / 128, 1), 128>>>(sdw, out, HDIM, FS);

    // Expert path: fused gate+up (gathered), then down + weighted atomic add
    k_gateup<1><<<dim3(FE / 64, T_TOK / 128, NEXP), 128>>>(x, egw, euw, FE, HDIM);
    k_down<1><<<dim3(HDIM / 128, T_TOK / 128, NEXP), 128>>>(edw, out, HDIM, FE);
}